// round 4
// baseline (speedup 1.0000x reference)
#include <cuda_runtime.h>
#include <cuda_bf16.h>
#include <math.h>
#include <stdint.h>

// ---------------- problem dims ----------------
#define BQ   1024
#define TT   64
#define HD   512
#define H3   1536
#define MGI  (BQ * TT)
#define KTOT 1536               // K' = 3 * 512 (bf16x3 split folded into K)
#define LN_EPS 1e-5f

#define BK 32
#define KITERS (KTOT / BK)      // 48
#define SA 40                   // padded smem row stride (bf16)
#define NSTAGE 4

// ---------------- device scratch ----------------
__device__ __nv_bfloat16 g_Agi[(size_t)MGI * KTOT];
__device__ float         g_gi [(size_t)MGI * H3];     // interleaved cols, biases folded
__device__ __nv_bfloat16 g_W2ih[(size_t)H3 * KTOT];   // gate-interleaved rows, [Wh|Wh|Wl]
__device__ __nv_bfloat16 g_W2hh[(size_t)H3 * KTOT];
__device__ __nv_bfloat16 g_h2[(size_t)BQ * KTOT];     // [hh | hl | hh]
__device__ float         g_h  [(size_t)BQ * HD];
__device__ float         g_bsum[H3];                  // interleaved b_ih + b_hh(r,z)
__device__ unsigned char g_active[TT * BQ];

// ---------------- helpers ----------------
__device__ __forceinline__ uint32_t smem_u32(const void* p) {
    uint32_t a;
    asm("{ .reg .u64 t; cvta.to.shared.u64 t, %1; cvt.u32.u64 %0, t; }" : "=r"(a) : "l"(p));
    return a;
}
#define CP_ASYNC16(dst, src) \
    asm volatile("cp.async.cg.shared.global [%0], [%1], 16;" :: "r"(dst), "l"(src))
#define CP_COMMIT() asm volatile("cp.async.commit_group;" ::: "memory")
#define CP_WAIT0()  asm volatile("cp.async.wait_group 0;" ::: "memory")
#define CP_WAIT1()  asm volatile("cp.async.wait_group 1;" ::: "memory")
#define CP_WAIT2()  asm volatile("cp.async.wait_group 2;" ::: "memory")

__device__ __forceinline__ void mma16816(float* c, const uint32_t* a,
                                         uint32_t b0, uint32_t b1)
{
    asm volatile(
        "mma.sync.aligned.m16n8k16.row.col.f32.bf16.bf16.f32 "
        "{%0,%1,%2,%3}, {%4,%5,%6,%7}, {%8,%9}, {%0,%1,%2,%3};"
        : "+f"(c[0]), "+f"(c[1]), "+f"(c[2]), "+f"(c[3])
        : "r"(a[0]), "r"(a[1]), "r"(a[2]), "r"(a[3]), "r"(b0), "r"(b1));
}

// ===========================================================================
// Big GEMM (gi): out[M, H3] = A[M,KTOT] x B[H3,KTOT]^T + bias, tile 128x128,
// 4-stage cp.async, 256 threads, grid (H3/128, M/128)
// ===========================================================================
#define BBM 128
#define BBN 128
#define BSTAGE ((BBM + BBN) * SA * 2)   // bytes per stage

__global__ __launch_bounds__(256)
void gemm_big(const __nv_bfloat16* __restrict__ A,
              const __nv_bfloat16* __restrict__ B,
              const float* __restrict__ bias,
              float* __restrict__ out)
{
    extern __shared__ __align__(16) char dsm[];
    const uint32_t sbase = smem_u32(dsm);

    const int tid  = threadIdx.x;
    const int lane = tid & 31;
    const int w    = tid >> 5;
    const int wr   = w & 1;
    const int wc   = w >> 1;
    const int qr   = lane >> 2;
    const int qc   = lane & 3;
    const int col0 = blockIdx.x * BBN;
    const int row0 = blockIdx.y * BBM;

    // loader: 4 chunks/thread
    const __nv_bfloat16* srcp[4];
    uint32_t soff[4];
    #pragma unroll
    for (int j = 0; j < 4; j++) {
        int idx  = tid + 256 * j;
        int arow = idx >> 2;
        int seg  = (idx & 3) * 8;
        if (arow < BBM) {
            srcp[j] = A + (size_t)(row0 + arow) * KTOT + seg;
            soff[j] = (uint32_t)(arow * SA + seg) * 2;
        } else {
            int brow = arow - BBM;
            srcp[j] = B + (size_t)(col0 + brow) * KTOT + seg;
            soff[j] = (uint32_t)(BBM * SA + brow * SA + seg) * 2;
        }
    }

    float acc[4][4][4];
    #pragma unroll
    for (int i = 0; i < 4; i++)
        #pragma unroll
        for (int j = 0; j < 4; j++)
            #pragma unroll
            for (int v = 0; v < 4; v++) acc[i][j][v] = 0.0f;

    // prologue: stages 0..2
    #pragma unroll
    for (int s = 0; s < NSTAGE - 1; s++) {
        uint32_t sb = sbase + s * BSTAGE;
        #pragma unroll
        for (int j = 0; j < 4; j++) CP_ASYNC16(sb + soff[j], srcp[j] + s * BK);
        CP_COMMIT();
    }

    #pragma unroll 1
    for (int kt = 0; kt < KITERS; kt++) {
        if (kt < KITERS - 2)      CP_WAIT2();
        else if (kt == KITERS - 2) CP_WAIT1();
        else                       CP_WAIT0();
        __syncthreads();

        if (kt + NSTAGE - 1 < KITERS) {
            int kc = kt + NSTAGE - 1;
            uint32_t sb = sbase + (kc & (NSTAGE - 1)) * BSTAGE;
            #pragma unroll
            for (int j = 0; j < 4; j++) CP_ASYNC16(sb + soff[j], srcp[j] + kc * BK);
            CP_COMMIT();
        }

        const __nv_bfloat16* As = (const __nv_bfloat16*)(dsm + (kt & (NSTAGE - 1)) * BSTAGE);
        const __nv_bfloat16* Bs = As + BBM * SA;

        #pragma unroll
        for (int ks = 0; ks < 2; ks++) {
            const int kb = ks * 16 + qc * 2;
            uint32_t afr[4][4];
            #pragma unroll
            for (int mi = 0; mi < 4; mi++) {
                int r = wr * 64 + mi * 16 + qr;
                afr[mi][0] = *(const uint32_t*)&As[r * SA + kb];
                afr[mi][1] = *(const uint32_t*)&As[(r + 8) * SA + kb];
                afr[mi][2] = *(const uint32_t*)&As[r * SA + kb + 8];
                afr[mi][3] = *(const uint32_t*)&As[(r + 8) * SA + kb + 8];
            }
            #pragma unroll
            for (int ni = 0; ni < 4; ni++) {
                int n = wc * 32 + ni * 8 + qr;
                uint32_t b0 = *(const uint32_t*)&Bs[n * SA + kb];
                uint32_t b1 = *(const uint32_t*)&Bs[n * SA + kb + 8];
                #pragma unroll
                for (int mi = 0; mi < 4; mi++)
                    mma16816(acc[mi][ni], afr[mi], b0, b1);
            }
        }
        __syncthreads();
    }

    #pragma unroll
    for (int mi = 0; mi < 4; mi++) {
        int r = row0 + wr * 64 + mi * 16 + qr;
        #pragma unroll
        for (int ni = 0; ni < 4; ni++) {
            int c = col0 + wc * 32 + ni * 8 + qc * 2;
            float2 bv = *(const float2*)(bias + c);
            float2 v0 = make_float2(acc[mi][ni][0] + bv.x, acc[mi][ni][1] + bv.y);
            float2 v1 = make_float2(acc[mi][ni][2] + bv.x, acc[mi][ni][3] + bv.y);
            *(float2*)(out + (size_t)r * H3 + c)       = v0;
            *(float2*)(out + (size_t)(r + 8) * H3 + c) = v1;
        }
    }
}

// ===========================================================================
// Fused gh GEMM + GRU update: tile 64x192, grid (H3/192=8, BQ/64=16)
// epilogue: gates via smem exchange -> h_new -> g_h, g_h2 (masked by active)
// ===========================================================================
#define FBM 64
#define FBN 192
#define FSTAGE ((FBM + FBN) * SA * 2)
#define SSTR 193                       // fp32 staging stride

__global__ __launch_bounds__(256)
void gemm_gh_fused(const __nv_bfloat16* __restrict__ A,   // g_h2
                   const __nv_bfloat16* __restrict__ B,   // g_W2hh (interleaved)
                   const float* __restrict__ gi,          // g_gi (interleaved, biased)
                   const float* __restrict__ b_hh,        // original layout
                   int t)
{
    extern __shared__ __align__(16) char dsm[];
    const uint32_t sbase = smem_u32(dsm);

    const int tid  = threadIdx.x;
    const int lane = tid & 31;
    const int w    = tid >> 5;
    const int wr   = w & 1;
    const int wc   = w >> 1;
    const int qr   = lane >> 2;
    const int qc   = lane & 3;
    const int col0 = blockIdx.x * FBN;
    const int row0 = blockIdx.y * FBM;

    const __nv_bfloat16* srcp[4];
    uint32_t soff[4];
    #pragma unroll
    for (int j = 0; j < 4; j++) {
        int idx  = tid + 256 * j;
        int arow = idx >> 2;
        int seg  = (idx & 3) * 8;
        if (arow < FBM) {
            srcp[j] = A + (size_t)(row0 + arow) * KTOT + seg;
            soff[j] = (uint32_t)(arow * SA + seg) * 2;
        } else {
            int brow = arow - FBM;
            srcp[j] = B + (size_t)(col0 + brow) * KTOT + seg;
            soff[j] = (uint32_t)(FBM * SA + brow * SA + seg) * 2;
        }
    }

    float acc[2][6][4];
    #pragma unroll
    for (int i = 0; i < 2; i++)
        #pragma unroll
        for (int j = 0; j < 6; j++)
            #pragma unroll
            for (int v = 0; v < 4; v++) acc[i][j][v] = 0.0f;

    #pragma unroll
    for (int s = 0; s < NSTAGE - 1; s++) {
        uint32_t sb = sbase + s * FSTAGE;
        #pragma unroll
        for (int j = 0; j < 4; j++) CP_ASYNC16(sb + soff[j], srcp[j] + s * BK);
        CP_COMMIT();
    }

    #pragma unroll 1
    for (int kt = 0; kt < KITERS; kt++) {
        if (kt < KITERS - 2)      CP_WAIT2();
        else if (kt == KITERS - 2) CP_WAIT1();
        else                       CP_WAIT0();
        __syncthreads();

        if (kt + NSTAGE - 1 < KITERS) {
            int kc = kt + NSTAGE - 1;
            uint32_t sb = sbase + (kc & (NSTAGE - 1)) * FSTAGE;
            #pragma unroll
            for (int j = 0; j < 4; j++) CP_ASYNC16(sb + soff[j], srcp[j] + kc * BK);
            CP_COMMIT();
        }

        const __nv_bfloat16* As = (const __nv_bfloat16*)(dsm + (kt & (NSTAGE - 1)) * FSTAGE);
        const __nv_bfloat16* Bs = As + FBM * SA;

        #pragma unroll
        for (int ks = 0; ks < 2; ks++) {
            const int kb = ks * 16 + qc * 2;
            uint32_t afr[2][4];
            #pragma unroll
            for (int mi = 0; mi < 2; mi++) {
                int r = wr * 32 + mi * 16 + qr;
                afr[mi][0] = *(const uint32_t*)&As[r * SA + kb];
                afr[mi][1] = *(const uint32_t*)&As[(r + 8) * SA + kb];
                afr[mi][2] = *(const uint32_t*)&As[r * SA + kb + 8];
                afr[mi][3] = *(const uint32_t*)&As[(r + 8) * SA + kb + 8];
            }
            #pragma unroll
            for (int ni = 0; ni < 6; ni++) {
                int n = wc * 48 + ni * 8 + qr;
                uint32_t b0 = *(const uint32_t*)&Bs[n * SA + kb];
                uint32_t b1 = *(const uint32_t*)&Bs[n * SA + kb + 8];
                #pragma unroll
                for (int mi = 0; mi < 2; mi++)
                    mma16816(acc[mi][ni], afr[mi], b0, b1);
            }
        }
        __syncthreads();
    }

    // ---- fused epilogue ----
    float* sst = (float*)dsm;      // [FBM][SSTR]
    #pragma unroll
    for (int mi = 0; mi < 2; mi++) {
        int r = wr * 32 + mi * 16 + qr;
        #pragma unroll
        for (int ni = 0; ni < 6; ni++) {
            int c = wc * 48 + ni * 8 + qc * 2;
            sst[r * SSTR + c]           = acc[mi][ni][0];
            sst[r * SSTR + c + 1]       = acc[mi][ni][1];
            sst[(r + 8) * SSTR + c]     = acc[mi][ni][2];
            sst[(r + 8) * SSTR + c + 1] = acc[mi][ni][3];
        }
    }
    __syncthreads();

    const unsigned char* actrow = g_active + (size_t)t * BQ;
    #pragma unroll
    for (int k = 0; k < (FBM * 64) / 256; k++) {
        int idx = tid + k * 256;
        int hl  = idx & 63;
        int rl  = idx >> 6;
        int b   = row0 + rl;
        if (!actrow[b]) continue;
        int hid = blockIdx.x * 64 + hl;

        float ghr = sst[rl * SSTR + 3 * hl];
        float ghz = sst[rl * SSTR + 3 * hl + 1];
        float ghn = sst[rl * SSTR + 3 * hl + 2];

        const float* gip = gi + ((size_t)t * BQ + b) * H3 + col0 + 3 * hl;
        float gir = gip[0], giz = gip[1], gin = gip[2];

        float r = 1.0f / (1.0f + expf(-(gir + ghr)));
        float z = 1.0f / (1.0f + expf(-(giz + ghz)));
        float n = tanhf(gin + r * (ghn + b_hh[1024 + hid]));

        float hold = g_h[(size_t)b * HD + hid];
        float hnew = (1.0f - z) * n + z * hold;

        g_h[(size_t)b * HD + hid] = hnew;
        __nv_bfloat16 hi = __float2bfloat16(hnew);
        __nv_bfloat16* h2row = g_h2 + (size_t)b * KTOT;
        h2row[hid]            = hi;
        h2row[HD + hid]       = __float2bfloat16(hnew - __bfloat162float(hi));
        h2row[2 * HD + hid]   = hi;
    }
}

// ===========================================================================
// prep kernels
// ===========================================================================
__global__ void prep_weights(const float* __restrict__ wih,
                             const float* __restrict__ whh)
{
    int n = blockIdx.x;                 // original row: gate g = n/512, hidden i = n%512
    int g = n >> 9, i = n & 511;
    int np = 3 * i + g;                 // interleaved row
    const float* src = (blockIdx.y == 0 ? wih : whh) + (size_t)n * HD;
    __nv_bfloat16* dst = (blockIdx.y == 0 ? g_W2ih : g_W2hh) + (size_t)np * KTOT;
    for (int k = threadIdx.x; k < HD; k += 128) {
        float x = src[k];
        __nv_bfloat16 hi = __float2bfloat16(x);
        float lo = x - __bfloat162float(hi);
        dst[k] = hi; dst[HD + k] = hi; dst[2 * HD + k] = __float2bfloat16(lo);
    }
}

__global__ void prep_bias_active(const float* __restrict__ b_ih,
                                 const float* __restrict__ b_hh,
                                 const int*   __restrict__ actions,
                                 const int*   __restrict__ stop_idx)
{
    int x = blockIdx.x * 256 + threadIdx.x;
    if (x < H3) {
        int g = x >> 9, i = x & 511;
        g_bsum[3 * i + g] = b_ih[x] + (g < 2 ? b_hh[x] : 0.0f);
    }
    if (x < BQ) {
        int b = x;
        int si = stop_idx[b];
        bool done = false;
        for (int t = 0; t < TT; t++) {
            int a = actions[b * TT + t];
            bool is_stop = (a == si) || (a < 0);
            g_active[t * BQ + b] = (!done && !is_stop) ? 1 : 0;
            done = done || is_stop;
        }
    }
}

__global__ void prep_agi(const int* __restrict__ actions,
                         const float* __restrict__ edge_tokens, int E)
{
    int m = blockIdx.x;
    int t = m >> 10, b = m & (BQ - 1);
    int a = actions[b * TT + t];
    a = a < 0 ? 0 : (a >= E ? E - 1 : a);
    const float* src = edge_tokens + (size_t)a * HD;
    __nv_bfloat16* dst = g_Agi + (size_t)m * KTOT;
    for (int k = threadIdx.x; k < HD; k += 128) {
        float x = src[k];
        __nv_bfloat16 hi = __float2bfloat16(x);
        float lo = x - __bfloat162float(hi);
        dst[k] = hi; dst[HD + k] = __float2bfloat16(lo); dst[2 * HD + k] = hi;
    }
}

// ===========================================================================
// LN helpers + init + ln_emit
// ===========================================================================
__device__ __forceinline__ float block_sum_256(float v, float* red)
{
    int lane = threadIdx.x & 31, w = threadIdx.x >> 5;
    #pragma unroll
    for (int o = 16; o > 0; o >>= 1) v += __shfl_xor_sync(0xffffffffu, v, o);
    if (lane == 0) red[w] = v;
    __syncthreads();
    if (w == 0) {
        float x = (lane < 8) ? red[lane] : 0.0f;
        #pragma unroll
        for (int o = 4; o > 0; o >>= 1) x += __shfl_xor_sync(0xffffffffu, x, o);
        if (lane == 0) red[0] = x;
    }
    __syncthreads();
    float r = red[0];
    __syncthreads();
    return r;
}

__device__ __forceinline__ void write_h2(__nv_bfloat16* h2row, int i, float v)
{
    __nv_bfloat16 hi = __float2bfloat16(v);
    h2row[i] = hi;
    h2row[HD + i] = __float2bfloat16(v - __bfloat162float(hi));
    h2row[2 * HD + i] = hi;
}

__global__ void init_kernel(const float* __restrict__ question,
                            const float* __restrict__ node_tokens,
                            const int*   __restrict__ locals,
                            const int*   __restrict__ ptr,
                            const float* __restrict__ ln_w,
                            const float* __restrict__ ln_b)
{
    __shared__ float red[8];
    int b = blockIdx.x, tid = threadIdx.x;
    int p0 = ptr[b], p1 = ptr[b + 1];
    int cnt = p1 - p0;
    float inv = 1.0f / (float)(cnt > 0 ? cnt : 1);

    float s0 = 0.0f, s1 = 0.0f;
    for (int j = p0; j < p1; j++) {
        const float* nrow = node_tokens + (size_t)locals[j] * HD;
        s0 += nrow[tid]; s1 += nrow[tid + 256];
    }
    const float* q = question + (size_t)b * HD;
    float x0 = q[tid] + s0 * inv, x1 = q[tid + 256] + s1 * inv;

    float mean = block_sum_256(x0 + x1, red) * (1.0f / HD);
    float d0 = x0 - mean, d1 = x1 - mean;
    float var = block_sum_256(d0 * d0 + d1 * d1, red) * (1.0f / HD);
    float rstd = rsqrtf(var + LN_EPS);

    float v0 = d0 * rstd * ln_w[tid] + ln_b[tid];
    float v1 = d1 * rstd * ln_w[tid + 256] + ln_b[tid + 256];
    float* hrow = g_h + (size_t)b * HD;
    hrow[tid] = v0; hrow[tid + 256] = v1;
    __nv_bfloat16* h2row = g_h2 + (size_t)b * KTOT;
    write_h2(h2row, tid, v0);
    write_h2(h2row, tid + 256, v1);
}

__global__ void ln_emit(const float* __restrict__ ln_w,
                        const float* __restrict__ ln_b,
                        float* __restrict__ out, int t)
{
    __shared__ float red[8];
    int b = blockIdx.x, tid = threadIdx.x;
    const float* hrow = g_h + (size_t)b * HD;
    float h0 = hrow[tid], h1 = hrow[tid + 256];

    float mean = block_sum_256(h0 + h1, red) * (1.0f / HD);
    float d0 = h0 - mean, d1 = h1 - mean;
    float var = block_sum_256(d0 * d0 + d1 * d1, red) * (1.0f / HD);
    float rstd = rsqrtf(var + LN_EPS);

    float* orow = out + ((size_t)b * TT + t) * HD;
    orow[tid]       = d0 * rstd * ln_w[tid] + ln_b[tid];
    orow[tid + 256] = d1 * rstd * ln_w[tid + 256] + ln_b[tid + 256];
}

// ===========================================================================
// launch
// ===========================================================================
extern "C" void kernel_launch(void* const* d_in, const int* in_sizes, int n_in,
                              void* d_out, int out_size)
{
    const int*   actions      = (const int*)  d_in[0];
    const float* edge_tokens  = (const float*)d_in[1];
    const int*   stop_indices = (const int*)  d_in[2];
    const float* question     = (const float*)d_in[3];
    const float* node_tokens  = (const float*)d_in[4];
    const int*   start_locals = (const int*)  d_in[5];
    const int*   start_ptr    = (const int*)  d_in[6];
    const float* w_ih         = (const float*)d_in[7];
    const float* w_hh         = (const float*)d_in[8];
    const float* b_ih         = (const float*)d_in[9];
    const float* b_hh         = (const float*)d_in[10];
    const float* ln_w         = (const float*)d_in[11];
    const float* ln_b         = (const float*)d_in[12];
    float* out = (float*)d_out;
    const int E = in_sizes[1] / HD;

    void *pAgi, *pWih, *pWhh, *pH2, *pGi, *pBsum;
    cudaGetSymbolAddress(&pAgi, g_Agi);
    cudaGetSymbolAddress(&pWih, g_W2ih);
    cudaGetSymbolAddress(&pWhh, g_W2hh);
    cudaGetSymbolAddress(&pH2,  g_h2);
    cudaGetSymbolAddress(&pGi,  g_gi);
    cudaGetSymbolAddress(&pBsum, g_bsum);

    const int big_smem = NSTAGE * BSTAGE;   // 81920
    const int fus_smem = NSTAGE * FSTAGE;   // 81920
    cudaFuncSetAttribute(gemm_big, cudaFuncAttributeMaxDynamicSharedMemorySize, big_smem);
    cudaFuncSetAttribute(gemm_gh_fused, cudaFuncAttributeMaxDynamicSharedMemorySize, fus_smem);

    // prep
    prep_weights<<<dim3(H3, 2), 128>>>(w_ih, w_hh);
    prep_bias_active<<<(H3 + 255) / 256, 256>>>(b_ih, b_hh, actions, stop_indices);
    prep_agi<<<MGI, 128>>>(actions, edge_tokens, E);
    init_kernel<<<BQ, 256>>>(question, node_tokens, start_locals, start_ptr, ln_w, ln_b);

    // batched gi GEMM (interleaved cols, biases folded)
    gemm_big<<<dim3(H3 / BBN, MGI / BBM), 256, big_smem>>>(
        (const __nv_bfloat16*)pAgi, (const __nv_bfloat16*)pWih,
        (const float*)pBsum, (float*)pGi);

    // sequential loop
    for (int t = 0; t < TT; t++) {
        ln_emit<<<BQ, 256>>>(ln_w, ln_b, out, t);
        if (t < TT - 1) {
            gemm_gh_fused<<<dim3(H3 / FBN, BQ / FBM), 256, fus_smem>>>(
                (const __nv_bfloat16*)pH2, (const __nv_bfloat16*)pWhh,
                (const float*)pGi, b_hh, t);
        }
    }
}

// round 5
// speedup vs baseline: 1.0538x; 1.0538x over previous
#include <cuda_runtime.h>
#include <cuda_bf16.h>
#include <math.h>
#include <stdint.h>

// ---------------- problem dims ----------------
#define BQ   1024
#define TT   64
#define HD   512
#define H3   1536
#define MGI  (BQ * TT)
#define KTOT 1536               // K' = 3 * 512 (bf16x3 split folded into K)
#define LN_EPS 1e-5f

#define BK 32
#define KITERS (KTOT / BK)      // 48
#define SA 40                   // padded smem row stride (bf16)
#define NSTAGE 4

// big (gi) GEMM tile
#define BBM 128
#define BBN 128
#define BSTAGE ((BBM + BBN) * SA * 2)   // 20480
#define BIG_SMEM (NSTAGE * BSTAGE)      // 81920

// persistent loop tile
#define PBM 128
#define PBN 96
#define PSTAGE ((PBM + PBN) * SA * 2)   // 17920
#define PSMEM (NSTAGE * PSTAGE)         // 71680
#define PCTAS 128
#define SSTR 97

// ---------------- device scratch ----------------
__device__ __nv_bfloat16 g_Agi[(size_t)MGI * KTOT];
__device__ float         g_gi [(size_t)MGI * H3];     // gate-interleaved cols, biases folded
__device__ __nv_bfloat16 g_W2ih[(size_t)H3 * KTOT];   // gate-interleaved rows, [Wh|Wh|Wl]
__device__ __nv_bfloat16 g_W2hh[(size_t)H3 * KTOT];
__device__ __nv_bfloat16 g_h2[(size_t)BQ * KTOT];     // [hh | hl | hh]
__device__ float         g_h  [(size_t)BQ * HD];
__device__ float         g_bsum[H3];
__device__ unsigned char g_active[TT * BQ];
__device__ unsigned int  g_barctr;

// ---------------- helpers ----------------
__device__ __forceinline__ uint32_t smem_u32(const void* p) {
    uint32_t a;
    asm("{ .reg .u64 t; cvta.to.shared.u64 t, %1; cvt.u32.u64 %0, t; }" : "=r"(a) : "l"(p));
    return a;
}
#define CP_ASYNC16(dst, src) \
    asm volatile("cp.async.cg.shared.global [%0], [%1], 16;" :: "r"(dst), "l"(src))
#define CP_COMMIT() asm volatile("cp.async.commit_group;" ::: "memory")
#define CP_WAIT0()  asm volatile("cp.async.wait_group 0;" ::: "memory")
#define CP_WAIT1()  asm volatile("cp.async.wait_group 1;" ::: "memory")
#define CP_WAIT2()  asm volatile("cp.async.wait_group 2;" ::: "memory")

__device__ __forceinline__ void mma16816(float* c, const uint32_t* a,
                                         uint32_t b0, uint32_t b1)
{
    asm volatile(
        "mma.sync.aligned.m16n8k16.row.col.f32.bf16.bf16.f32 "
        "{%0,%1,%2,%3}, {%4,%5,%6,%7}, {%8,%9}, {%0,%1,%2,%3};"
        : "+f"(c[0]), "+f"(c[1]), "+f"(c[2]), "+f"(c[3])
        : "r"(a[0]), "r"(a[1]), "r"(a[2]), "r"(a[3]), "r"(b0), "r"(b1));
}
__device__ __forceinline__ void ldsm4(uint32_t* r, uint32_t addr) {
    asm volatile("ldmatrix.sync.aligned.m8n8.x4.shared.b16 {%0,%1,%2,%3}, [%4];"
                 : "=r"(r[0]), "=r"(r[1]), "=r"(r[2]), "=r"(r[3]) : "r"(addr));
}
__device__ __forceinline__ void ldsm2(uint32_t* r, uint32_t addr) {
    asm volatile("ldmatrix.sync.aligned.m8n8.x2.shared.b16 {%0,%1}, [%2];"
                 : "=r"(r[0]), "=r"(r[1]) : "r"(addr));
}
__device__ __forceinline__ unsigned ld_acq(unsigned* p) {
    unsigned v;
    asm volatile("ld.acquire.gpu.u32 %0, [%1];" : "=r"(v) : "l"(p));
    return v;
}
__device__ __forceinline__ void grid_bar(unsigned target) {
    __syncthreads();
    if (threadIdx.x == 0) {
        __threadfence();                       // release (orders our writes)
        atomicAdd(&g_barctr, 1u);
        while (ld_acq(&g_barctr) < target) {}
        __threadfence();                       // IVALL: invalidate stale L1
    }
    __syncthreads();
}

// ===========================================================================
// Big GEMM (gi): out[M, H3] = A x B^T + bias ; tile 128x128, ldmatrix, 4-stage
// grid = (12, 512)
// ===========================================================================
__global__ __launch_bounds__(256)
void gemm_big(const __nv_bfloat16* __restrict__ A,
              const __nv_bfloat16* __restrict__ B,
              const float* __restrict__ bias,
              float* __restrict__ out)
{
    extern __shared__ __align__(16) char dsm[];
    const uint32_t sbase = smem_u32(dsm);

    const int tid  = threadIdx.x;
    const int lane = tid & 31;
    const int w    = tid >> 5;
    const int wr   = w & 1;
    const int wc   = w >> 1;
    const int qr   = lane >> 2;
    const int qc   = lane & 3;
    const int col0 = blockIdx.x * BBN;
    const int row0 = blockIdx.y * BBM;

    const __nv_bfloat16* srcp[4];
    uint32_t soff[4];
    #pragma unroll
    for (int j = 0; j < 4; j++) {
        int idx  = tid + 256 * j;
        int arow = idx >> 2;
        int seg  = (idx & 3) * 8;
        if (arow < BBM) {
            srcp[j] = A + (size_t)(row0 + arow) * KTOT + seg;
            soff[j] = (uint32_t)(arow * SA + seg) * 2;
        } else {
            int brow = arow - BBM;
            srcp[j] = B + (size_t)(col0 + brow) * KTOT + seg;
            soff[j] = (uint32_t)((BBM + brow) * SA + seg) * 2;
        }
    }

    // ldmatrix per-thread base offsets (bytes)
    uint32_t aoff[4], boff[2];
    #pragma unroll
    for (int mi = 0; mi < 4; mi++)
        aoff[mi] = (uint32_t)((wr * 64 + mi * 16 + (lane & 7) + 8 * ((lane >> 3) & 1)) * SA
                              + 8 * (lane >> 4)) * 2;
    #pragma unroll
    for (int p = 0; p < 2; p++)
        boff[p] = (uint32_t)((BBM + wc * 32 + p * 16 + (lane & 7) + 8 * (lane >> 4)) * SA
                             + 8 * ((lane >> 3) & 1)) * 2;

    float acc[4][4][4];
    #pragma unroll
    for (int i = 0; i < 4; i++)
        #pragma unroll
        for (int j = 0; j < 4; j++)
            #pragma unroll
            for (int v = 0; v < 4; v++) acc[i][j][v] = 0.0f;

    #pragma unroll
    for (int s = 0; s < NSTAGE - 1; s++) {
        uint32_t sb = sbase + s * BSTAGE;
        #pragma unroll
        for (int j = 0; j < 4; j++) CP_ASYNC16(sb + soff[j], srcp[j] + s * BK);
        CP_COMMIT();
    }

    #pragma unroll 1
    for (int kt = 0; kt < KITERS; kt++) {
        if (kt < KITERS - 2)       CP_WAIT2();
        else if (kt == KITERS - 2) CP_WAIT1();
        else                       CP_WAIT0();
        __syncthreads();

        if (kt + NSTAGE - 1 < KITERS) {
            int kc = kt + NSTAGE - 1;
            uint32_t sb = sbase + (kc & (NSTAGE - 1)) * BSTAGE;
            #pragma unroll
            for (int j = 0; j < 4; j++) CP_ASYNC16(sb + soff[j], srcp[j] + kc * BK);
            CP_COMMIT();
        }

        uint32_t sst = sbase + (kt & (NSTAGE - 1)) * BSTAGE;
        #pragma unroll
        for (int ks = 0; ks < 2; ks++) {
            uint32_t kb2 = ks * 32;   // bytes
            uint32_t af[4][4], bf[2][4];
            #pragma unroll
            for (int mi = 0; mi < 4; mi++) ldsm4(af[mi], sst + aoff[mi] + kb2);
            #pragma unroll
            for (int p = 0; p < 2; p++)    ldsm4(bf[p], sst + boff[p] + kb2);
            #pragma unroll
            for (int ni = 0; ni < 4; ni++) {
                uint32_t b0 = bf[ni >> 1][(ni & 1) * 2];
                uint32_t b1 = bf[ni >> 1][(ni & 1) * 2 + 1];
                #pragma unroll
                for (int mi = 0; mi < 4; mi++)
                    mma16816(acc[mi][ni], af[mi], b0, b1);
            }
        }
        __syncthreads();
    }

    #pragma unroll
    for (int mi = 0; mi < 4; mi++) {
        int r = row0 + wr * 64 + mi * 16 + qr;
        #pragma unroll
        for (int ni = 0; ni < 4; ni++) {
            int c = col0 + wc * 32 + ni * 8 + qc * 2;
            float2 bv = *(const float2*)(bias + c);
            float2 v0 = make_float2(acc[mi][ni][0] + bv.x, acc[mi][ni][1] + bv.y);
            float2 v1 = make_float2(acc[mi][ni][2] + bv.x, acc[mi][ni][3] + bv.y);
            *(float2*)(out + (size_t)r * H3 + c)       = v0;
            *(float2*)(out + (size_t)(r + 8) * H3 + c) = v1;
        }
    }
}

// ===========================================================================
// Persistent loop kernel: 128 CTAs, per step: [LN emit] bar [gh GEMM+GRU] bar
// tile 128x96 (8 m-tiles x 16 n-tiles = 128 tiles, one per CTA)
// ===========================================================================
__global__ __launch_bounds__(256)
void persist_loop(const float* __restrict__ ln_w,
                  const float* __restrict__ ln_b,
                  const float* __restrict__ b_hh,
                  float* __restrict__ out)
{
    extern __shared__ __align__(16) char dsm[];
    const uint32_t sbase = smem_u32(dsm);

    const int tid  = threadIdx.x;
    const int lane = tid & 31;
    const int w    = tid >> 5;
    const int wr   = w & 1;
    const int wc   = w >> 1;
    const int qr   = lane >> 2;
    const int qc   = lane & 3;
    const int cid  = blockIdx.x;
    const int row0 = (cid >> 4) * PBM;
    const int ntile = cid & 15;
    const int col0 = ntile * PBN;
    const int hid0 = ntile * 32;
    const int lnrow = cid * 8 + w;     // exactly 1024 rows over 128x8 warps

    // loader: 896 16B-chunks, 256 threads x 4 (last 128 invalid)
    const __nv_bfloat16* srcp[4];
    uint32_t soff[4];
    bool sval[4];
    #pragma unroll
    for (int j = 0; j < 4; j++) {
        int idx  = tid + 256 * j;
        sval[j]  = idx < (PBM + PBN) * 4;
        int arow = idx >> 2;
        int seg  = (idx & 3) * 8;
        if (arow < PBM) {
            srcp[j] = g_h2 + (size_t)(row0 + arow) * KTOT + seg;
            soff[j] = (uint32_t)(arow * SA + seg) * 2;
        } else {
            int brow = arow - PBM;
            if (brow > PBN - 1) brow = PBN - 1;
            srcp[j] = g_W2hh + (size_t)(col0 + brow) * KTOT + seg;
            soff[j] = (uint32_t)((PBM + brow) * SA + seg) * 2;
        }
    }

    uint32_t aoff[4], boff4, boff2;
    #pragma unroll
    for (int mi = 0; mi < 4; mi++)
        aoff[mi] = (uint32_t)((wr * 64 + mi * 16 + (lane & 7) + 8 * ((lane >> 3) & 1)) * SA
                              + 8 * (lane >> 4)) * 2;
    boff4 = (uint32_t)((PBM + wc * 24 + (lane & 7) + 8 * (lane >> 4)) * SA
                       + 8 * ((lane >> 3) & 1)) * 2;
    boff2 = (uint32_t)((PBM + wc * 24 + 16 + (lane & 7)) * SA
                       + 8 * ((lane >> 3) & 1)) * 2;

    unsigned ph = 0;

    #pragma unroll 1
    for (int t = 0; t < TT; t++) {
        // ---------- phase A: out[:, t] = LN(h) ; one row per warp ----------
        {
            const float* hp = g_h + (size_t)lnrow * HD;
            float4 v[4];
            #pragma unroll
            for (int j = 0; j < 4; j++) v[j] = ((const float4*)hp)[lane + 32 * j];
            float s = 0.0f;
            #pragma unroll
            for (int j = 0; j < 4; j++) s += v[j].x + v[j].y + v[j].z + v[j].w;
            #pragma unroll
            for (int o = 16; o > 0; o >>= 1) s += __shfl_xor_sync(0xffffffffu, s, o);
            float mean = s * (1.0f / HD);
            float q = 0.0f;
            #pragma unroll
            for (int j = 0; j < 4; j++) {
                float a0 = v[j].x - mean, a1 = v[j].y - mean;
                float a2 = v[j].z - mean, a3 = v[j].w - mean;
                q += a0 * a0 + a1 * a1 + a2 * a2 + a3 * a3;
            }
            #pragma unroll
            for (int o = 16; o > 0; o >>= 1) q += __shfl_xor_sync(0xffffffffu, q, o);
            float rstd = rsqrtf(q * (1.0f / HD) + LN_EPS);
            float* orow = out + ((size_t)lnrow * TT + t) * HD;
            #pragma unroll
            for (int j = 0; j < 4; j++) {
                float4 lw = ((const float4*)ln_w)[lane + 32 * j];
                float4 lb = ((const float4*)ln_b)[lane + 32 * j];
                float4 o;
                o.x = (v[j].x - mean) * rstd * lw.x + lb.x;
                o.y = (v[j].y - mean) * rstd * lw.y + lb.y;
                o.z = (v[j].z - mean) * rstd * lw.z + lb.z;
                o.w = (v[j].w - mean) * rstd * lw.w + lb.w;
                ((float4*)orow)[lane + 32 * j] = o;
            }
        }
        grid_bar(++ph * PCTAS);
        if (t == TT - 1) break;

        // ---------- phase B: gh GEMM (128x96, K=1536) + fused GRU update ----------
        {
            float acc[4][3][4];
            #pragma unroll
            for (int i = 0; i < 4; i++)
                #pragma unroll
                for (int j = 0; j < 3; j++)
                    #pragma unroll
                    for (int v = 0; v < 4; v++) acc[i][j][v] = 0.0f;

            #pragma unroll
            for (int s = 0; s < NSTAGE - 1; s++) {
                uint32_t sb = sbase + s * PSTAGE;
                #pragma unroll
                for (int j = 0; j < 4; j++)
                    if (sval[j]) CP_ASYNC16(sb + soff[j], srcp[j] + s * BK);
                CP_COMMIT();
            }

            #pragma unroll 1
            for (int kt = 0; kt < KITERS; kt++) {
                if (kt < KITERS - 2)       CP_WAIT2();
                else if (kt == KITERS - 2) CP_WAIT1();
                else                       CP_WAIT0();
                __syncthreads();

                if (kt + NSTAGE - 1 < KITERS) {
                    int kc = kt + NSTAGE - 1;
                    uint32_t sb = sbase + (kc & (NSTAGE - 1)) * PSTAGE;
                    #pragma unroll
                    for (int j = 0; j < 4; j++)
                        if (sval[j]) CP_ASYNC16(sb + soff[j], srcp[j] + kc * BK);
                    CP_COMMIT();
                }

                uint32_t sst = sbase + (kt & (NSTAGE - 1)) * PSTAGE;
                #pragma unroll
                for (int ks = 0; ks < 2; ks++) {
                    uint32_t kb2 = ks * 32;
                    uint32_t af[4][4], bfa[4], bfb[2];
                    #pragma unroll
                    for (int mi = 0; mi < 4; mi++) ldsm4(af[mi], sst + aoff[mi] + kb2);
                    ldsm4(bfa, sst + boff4 + kb2);
                    ldsm2(bfb, sst + boff2 + kb2);
                    #pragma unroll
                    for (int ni = 0; ni < 3; ni++) {
                        uint32_t b0 = (ni < 2) ? bfa[ni * 2]     : bfb[0];
                        uint32_t b1 = (ni < 2) ? bfa[ni * 2 + 1] : bfb[1];
                        #pragma unroll
                        for (int mi = 0; mi < 4; mi++)
                            mma16816(acc[mi][ni], af[mi], b0, b1);
                    }
                }
                __syncthreads();
            }

            // stage accs to smem
            float* sst = (float*)dsm;
            #pragma unroll
            for (int mi = 0; mi < 4; mi++) {
                int r = wr * 64 + mi * 16 + qr;
                #pragma unroll
                for (int ni = 0; ni < 3; ni++) {
                    int c = wc * 24 + ni * 8 + qc * 2;
                    sst[r * SSTR + c]           = acc[mi][ni][0];
                    sst[r * SSTR + c + 1]       = acc[mi][ni][1];
                    sst[(r + 8) * SSTR + c]     = acc[mi][ni][2];
                    sst[(r + 8) * SSTR + c + 1] = acc[mi][ni][3];
                }
            }
            __syncthreads();

            // GRU update: 128 rows x 32 hidden per CTA
            const unsigned char* actrow = g_active + (size_t)t * BQ;
            #pragma unroll
            for (int k = 0; k < (PBM * 32) / 256; k++) {
                int idx = tid + k * 256;
                int rl  = idx >> 5;
                int j   = idx & 31;
                int b   = row0 + rl;
                if (!actrow[b]) continue;
                int hid = hid0 + j;

                float ghr = sst[rl * SSTR + 3 * j];
                float ghz = sst[rl * SSTR + 3 * j + 1];
                float ghn = sst[rl * SSTR + 3 * j + 2];

                const float* gip = g_gi + ((size_t)t * BQ + b) * H3 + col0 + 3 * j;
                float r = 1.0f / (1.0f + expf(-(gip[0] + ghr)));
                float z = 1.0f / (1.0f + expf(-(gip[1] + ghz)));
                float n = tanhf(gip[2] + r * (ghn + b_hh[1024 + hid]));

                float hold = g_h[(size_t)b * HD + hid];
                float hnew = (1.0f - z) * n + z * hold;

                g_h[(size_t)b * HD + hid] = hnew;
                __nv_bfloat16 hi = __float2bfloat16(hnew);
                __nv_bfloat16* h2row = g_h2 + (size_t)b * KTOT;
                h2row[hid]          = hi;
                h2row[HD + hid]     = __float2bfloat16(hnew - __bfloat162float(hi));
                h2row[2 * HD + hid] = hi;
            }
        }
        grid_bar(++ph * PCTAS);
    }
}

// ===========================================================================
// prep kernels
// ===========================================================================
__global__ void prep_weights(const float* __restrict__ wih,
                             const float* __restrict__ whh)
{
    int n = blockIdx.x;
    int g = n >> 9, i = n & 511;
    int np = 3 * i + g;
    const float* src = (blockIdx.y == 0 ? wih : whh) + (size_t)n * HD;
    __nv_bfloat16* dst = (blockIdx.y == 0 ? g_W2ih : g_W2hh) + (size_t)np * KTOT;
    for (int k = threadIdx.x; k < HD; k += 128) {
        float x = src[k];
        __nv_bfloat16 hi = __float2bfloat16(x);
        float lo = x - __bfloat162float(hi);
        dst[k] = hi; dst[HD + k] = hi; dst[2 * HD + k] = __float2bfloat16(lo);
    }
}

__global__ void prep_bias_active(const float* __restrict__ b_ih,
                                 const float* __restrict__ b_hh,
                                 const int*   __restrict__ actions,
                                 const int*   __restrict__ stop_idx)
{
    int x = blockIdx.x * 256 + threadIdx.x;
    if (x == 0) g_barctr = 0;
    if (x < H3) {
        int g = x >> 9, i = x & 511;
        g_bsum[3 * i + g] = b_ih[x] + (g < 2 ? b_hh[x] : 0.0f);
    }
    if (x < BQ) {
        int b = x;
        int si = stop_idx[b];
        bool done = false;
        for (int t = 0; t < TT; t++) {
            int a = actions[b * TT + t];
            bool is_stop = (a == si) || (a < 0);
            g_active[t * BQ + b] = (!done && !is_stop) ? 1 : 0;
            done = done || is_stop;
        }
    }
}

__global__ void prep_agi(const int* __restrict__ actions,
                         const float* __restrict__ edge_tokens, int E)
{
    int m = blockIdx.x;
    int t = m >> 10, b = m & (BQ - 1);
    int a = actions[b * TT + t];
    a = a < 0 ? 0 : (a >= E ? E - 1 : a);
    const float* src = edge_tokens + (size_t)a * HD;
    __nv_bfloat16* dst = g_Agi + (size_t)m * KTOT;
    for (int k = threadIdx.x; k < HD; k += 128) {
        float x = src[k];
        __nv_bfloat16 hi = __float2bfloat16(x);
        float lo = x - __bfloat162float(hi);
        dst[k] = hi; dst[HD + k] = __float2bfloat16(lo); dst[2 * HD + k] = hi;
    }
}

// ===========================================================================
// init
// ===========================================================================
__device__ __forceinline__ float block_sum_256(float v, float* red)
{
    int lane = threadIdx.x & 31, w = threadIdx.x >> 5;
    #pragma unroll
    for (int o = 16; o > 0; o >>= 1) v += __shfl_xor_sync(0xffffffffu, v, o);
    if (lane == 0) red[w] = v;
    __syncthreads();
    if (w == 0) {
        float x = (lane < 8) ? red[lane] : 0.0f;
        #pragma unroll
        for (int o = 4; o > 0; o >>= 1) x += __shfl_xor_sync(0xffffffffu, x, o);
        if (lane == 0) red[0] = x;
    }
    __syncthreads();
    float r = red[0];
    __syncthreads();
    return r;
}

__global__ void init_kernel(const float* __restrict__ question,
                            const float* __restrict__ node_tokens,
                            const int*   __restrict__ locals,
                            const int*   __restrict__ ptr,
                            const float* __restrict__ ln_w,
                            const float* __restrict__ ln_b)
{
    __shared__ float red[8];
    int b = blockIdx.x, tid = threadIdx.x;
    int p0 = ptr[b], p1 = ptr[b + 1];
    int cnt = p1 - p0;
    float inv = 1.0f / (float)(cnt > 0 ? cnt : 1);

    float s0 = 0.0f, s1 = 0.0f;
    for (int j = p0; j < p1; j++) {
        const float* nrow = node_tokens + (size_t)locals[j] * HD;
        s0 += nrow[tid]; s1 += nrow[tid + 256];
    }
    const float* q = question + (size_t)b * HD;
    float x0 = q[tid] + s0 * inv, x1 = q[tid + 256] + s1 * inv;

    float mean = block_sum_256(x0 + x1, red) * (1.0f / HD);
    float d0 = x0 - mean, d1 = x1 - mean;
    float var = block_sum_256(d0 * d0 + d1 * d1, red) * (1.0f / HD);
    float rstd = rsqrtf(var + LN_EPS);

    float v0 = d0 * rstd * ln_w[tid] + ln_b[tid];
    float v1 = d1 * rstd * ln_w[tid + 256] + ln_b[tid + 256];
    float* hrow = g_h + (size_t)b * HD;
    hrow[tid] = v0; hrow[tid + 256] = v1;

    __nv_bfloat16* h2row = g_h2 + (size_t)b * KTOT;
    __nv_bfloat16 h0 = __float2bfloat16(v0);
    h2row[tid]            = h0;
    h2row[HD + tid]       = __float2bfloat16(v0 - __bfloat162float(h0));
    h2row[2 * HD + tid]   = h0;
    __nv_bfloat16 h1 = __float2bfloat16(v1);
    h2row[tid + 256]          = h1;
    h2row[HD + tid + 256]     = __float2bfloat16(v1 - __bfloat162float(h1));
    h2row[2 * HD + tid + 256] = h1;
}

// ===========================================================================
// launch
// ===========================================================================
extern "C" void kernel_launch(void* const* d_in, const int* in_sizes, int n_in,
                              void* d_out, int out_size)
{
    const int*   actions      = (const int*)  d_in[0];
    const float* edge_tokens  = (const float*)d_in[1];
    const int*   stop_indices = (const int*)  d_in[2];
    const float* question     = (const float*)d_in[3];
    const float* node_tokens  = (const float*)d_in[4];
    const int*   start_locals = (const int*)  d_in[5];
    const int*   start_ptr    = (const int*)  d_in[6];
    const float* w_ih         = (const float*)d_in[7];
    const float* w_hh         = (const float*)d_in[8];
    const float* b_ih         = (const float*)d_in[9];
    const float* b_hh         = (const float*)d_in[10];
    const float* ln_w         = (const float*)d_in[11];
    const float* ln_b         = (const float*)d_in[12];
    float* out = (float*)d_out;
    const int E = in_sizes[1] / HD;

    void *pAgi, *pWih, *pGi, *pBsum;
    cudaGetSymbolAddress(&pAgi, g_Agi);
    cudaGetSymbolAddress(&pWih, g_W2ih);
    cudaGetSymbolAddress(&pGi,  g_gi);
    cudaGetSymbolAddress(&pBsum, g_bsum);

    cudaFuncSetAttribute(gemm_big, cudaFuncAttributeMaxDynamicSharedMemorySize, BIG_SMEM);
    cudaFuncSetAttribute(persist_loop, cudaFuncAttributeMaxDynamicSharedMemorySize, PSMEM);

    prep_weights<<<dim3(H3, 2), 128>>>(w_ih, w_hh);
    prep_bias_active<<<(H3 + 255) / 256, 256>>>(b_ih, b_hh, actions, stop_indices);
    prep_agi<<<MGI, 128>>>(actions, edge_tokens, E);
    init_kernel<<<BQ, 256>>>(question, node_tokens, start_locals, start_ptr, ln_w, ln_b);

    gemm_big<<<dim3(H3 / BBN, MGI / BBM), 256, BIG_SMEM>>>(
        (const __nv_bfloat16*)pAgi, (const __nv_bfloat16*)pWih,
        (const float*)pBsum, (float*)pGi);

    persist_loop<<<PCTAS, 256, PSMEM>>>(ln_w, ln_b, b_hh, out);
}

// round 6
// speedup vs baseline: 1.3530x; 1.2839x over previous
#include <cuda_runtime.h>
#include <cuda_bf16.h>
#include <math.h>
#include <stdint.h>

// ---------------- problem dims ----------------
#define BQ   1024
#define TT   64
#define HD   512
#define H3   1536
#define MGI  (BQ * TT)
#define KTOT 1536               // K' = 3 * 512 (bf16x3 split folded into K)
#define LN_EPS 1e-5f

// ---- big (gi) GEMM tiling (unchanged from R5) ----
#define BK 32
#define KITERS (KTOT / BK)      // 48
#define SA 40
#define NSTAGE 4
#define BBM 128
#define BBN 128
#define BSTAGE ((BBM + BBN) * SA * 2)
#define BIG_SMEM (NSTAGE * BSTAGE)      // 81920

// ---- persistent loop tiling: 64x96, BK=64, 3 stages, 256 CTAs (2/SM) ----
#define LBM 64
#define LBN 96
#define LBK 64
#define LSA 72
#define LKIT (KTOT / LBK)               // 24
#define LROWS (LBM + LBN)               // 160
#define LSTAGE (LROWS * LSA * 2)        // 23040
#define LNST 3
#define LSMEM (LNST * LSTAGE)           // 69120
#define PCTAS 256
#define SSTR 97

// ---------------- device scratch ----------------
__device__ __nv_bfloat16 g_Agi[(size_t)MGI * KTOT];
__device__ float         g_gi [(size_t)MGI * H3];     // gate-interleaved cols, biases folded
__device__ __nv_bfloat16 g_W2ih[(size_t)H3 * KTOT];   // gate-interleaved rows, [Wh|Wh|Wl]
__device__ __nv_bfloat16 g_W2hh[(size_t)H3 * KTOT];
__device__ __nv_bfloat16 g_h2[2][(size_t)BQ * KTOT];  // ping-pong [hh | hl | hh]
__device__ float         g_h [2][(size_t)BQ * HD];
__device__ float         g_bsum[H3];
__device__ unsigned char g_active[TT * BQ];
__device__ unsigned int  g_barctr;

// ---------------- helpers ----------------
__device__ __forceinline__ uint32_t smem_u32(const void* p) {
    uint32_t a;
    asm("{ .reg .u64 t; cvta.to.shared.u64 t, %1; cvt.u32.u64 %0, t; }" : "=r"(a) : "l"(p));
    return a;
}
#define CP_ASYNC16(dst, src) \
    asm volatile("cp.async.cg.shared.global [%0], [%1], 16;" :: "r"(dst), "l"(src))
#define CP_COMMIT() asm volatile("cp.async.commit_group;" ::: "memory")
#define CP_WAIT0()  asm volatile("cp.async.wait_group 0;" ::: "memory")
#define CP_WAIT1()  asm volatile("cp.async.wait_group 1;" ::: "memory")
#define CP_WAIT2()  asm volatile("cp.async.wait_group 2;" ::: "memory")

__device__ __forceinline__ void mma16816(float* c, const uint32_t* a,
                                         uint32_t b0, uint32_t b1)
{
    asm volatile(
        "mma.sync.aligned.m16n8k16.row.col.f32.bf16.bf16.f32 "
        "{%0,%1,%2,%3}, {%4,%5,%6,%7}, {%8,%9}, {%0,%1,%2,%3};"
        : "+f"(c[0]), "+f"(c[1]), "+f"(c[2]), "+f"(c[3])
        : "r"(a[0]), "r"(a[1]), "r"(a[2]), "r"(a[3]), "r"(b0), "r"(b1));
}
__device__ __forceinline__ void ldsm4(uint32_t* r, uint32_t addr) {
    asm volatile("ldmatrix.sync.aligned.m8n8.x4.shared.b16 {%0,%1,%2,%3}, [%4];"
                 : "=r"(r[0]), "=r"(r[1]), "=r"(r[2]), "=r"(r[3]) : "r"(addr));
}
__device__ __forceinline__ void ldsm2(uint32_t* r, uint32_t addr) {
    asm volatile("ldmatrix.sync.aligned.m8n8.x2.shared.b16 {%0,%1}, [%2];"
                 : "=r"(r[0]), "=r"(r[1]) : "r"(addr));
}
__device__ __forceinline__ unsigned ld_acq(unsigned* p) {
    unsigned v;
    asm volatile("ld.acquire.gpu.u32 %0, [%1];" : "=r"(v) : "l"(p));
    return v;
}
__device__ __forceinline__ void grid_bar(unsigned target) {
    __syncthreads();
    if (threadIdx.x == 0) {
        __threadfence();
        atomicAdd(&g_barctr, 1u);
        while (ld_acq(&g_barctr) < target) {}
        __threadfence();                  // IVALL: drop stale L1 lines
    }
    __syncthreads();
}

// ===========================================================================
// Big GEMM (gi): out[M, H3] = A x B^T + bias ; tile 128x128 (R5, unchanged)
// ===========================================================================
__global__ __launch_bounds__(256)
void gemm_big(const __nv_bfloat16* __restrict__ A,
              const __nv_bfloat16* __restrict__ B,
              const float* __restrict__ bias,
              float* __restrict__ out)
{
    extern __shared__ __align__(16) char dsm[];
    const uint32_t sbase = smem_u32(dsm);

    const int tid  = threadIdx.x;
    const int lane = tid & 31;
    const int w    = tid >> 5;
    const int wr   = w & 1;
    const int wc   = w >> 1;
    const int qr   = lane >> 2;
    const int qc   = lane & 3;
    const int col0 = blockIdx.x * BBN;
    const int row0 = blockIdx.y * BBM;

    const __nv_bfloat16* srcp[4];
    uint32_t soff[4];
    #pragma unroll
    for (int j = 0; j < 4; j++) {
        int idx  = tid + 256 * j;
        int arow = idx >> 2;
        int seg  = (idx & 3) * 8;
        if (arow < BBM) {
            srcp[j] = A + (size_t)(row0 + arow) * KTOT + seg;
            soff[j] = (uint32_t)(arow * SA + seg) * 2;
        } else {
            int brow = arow - BBM;
            srcp[j] = B + (size_t)(col0 + brow) * KTOT + seg;
            soff[j] = (uint32_t)((BBM + brow) * SA + seg) * 2;
        }
    }

    uint32_t aoff[4], boff[2];
    #pragma unroll
    for (int mi = 0; mi < 4; mi++)
        aoff[mi] = (uint32_t)((wr * 64 + mi * 16 + (lane & 7) + 8 * ((lane >> 3) & 1)) * SA
                              + 8 * (lane >> 4)) * 2;
    #pragma unroll
    for (int p = 0; p < 2; p++)
        boff[p] = (uint32_t)((BBM + wc * 32 + p * 16 + (lane & 7) + 8 * (lane >> 4)) * SA
                             + 8 * ((lane >> 3) & 1)) * 2;

    float acc[4][4][4];
    #pragma unroll
    for (int i = 0; i < 4; i++)
        #pragma unroll
        for (int j = 0; j < 4; j++)
            #pragma unroll
            for (int v = 0; v < 4; v++) acc[i][j][v] = 0.0f;

    #pragma unroll
    for (int s = 0; s < NSTAGE - 1; s++) {
        uint32_t sb = sbase + s * BSTAGE;
        #pragma unroll
        for (int j = 0; j < 4; j++) CP_ASYNC16(sb + soff[j], srcp[j] + s * BK);
        CP_COMMIT();
    }

    #pragma unroll 1
    for (int kt = 0; kt < KITERS; kt++) {
        if (kt < KITERS - 2)       CP_WAIT2();
        else if (kt == KITERS - 2) CP_WAIT1();
        else                       CP_WAIT0();
        __syncthreads();

        if (kt + NSTAGE - 1 < KITERS) {
            int kc = kt + NSTAGE - 1;
            uint32_t sb = sbase + (kc & (NSTAGE - 1)) * BSTAGE;
            #pragma unroll
            for (int j = 0; j < 4; j++) CP_ASYNC16(sb + soff[j], srcp[j] + kc * BK);
            CP_COMMIT();
        }

        uint32_t sst = sbase + (kt & (NSTAGE - 1)) * BSTAGE;
        #pragma unroll
        for (int ks = 0; ks < 2; ks++) {
            uint32_t kb2 = ks * 32;
            uint32_t af[4][4], bf[2][4];
            #pragma unroll
            for (int mi = 0; mi < 4; mi++) ldsm4(af[mi], sst + aoff[mi] + kb2);
            #pragma unroll
            for (int p = 0; p < 2; p++)    ldsm4(bf[p], sst + boff[p] + kb2);
            #pragma unroll
            for (int ni = 0; ni < 4; ni++) {
                uint32_t b0 = bf[ni >> 1][(ni & 1) * 2];
                uint32_t b1 = bf[ni >> 1][(ni & 1) * 2 + 1];
                #pragma unroll
                for (int mi = 0; mi < 4; mi++)
                    mma16816(acc[mi][ni], af[mi], b0, b1);
            }
        }
        __syncthreads();
    }

    #pragma unroll
    for (int mi = 0; mi < 4; mi++) {
        int r = row0 + wr * 64 + mi * 16 + qr;
        #pragma unroll
        for (int ni = 0; ni < 4; ni++) {
            int c = col0 + wc * 32 + ni * 8 + qc * 2;
            float2 bv = *(const float2*)(bias + c);
            float2 v0 = make_float2(acc[mi][ni][0] + bv.x, acc[mi][ni][1] + bv.y);
            float2 v1 = make_float2(acc[mi][ni][2] + bv.x, acc[mi][ni][3] + bv.y);
            *(float2*)(out + (size_t)r * H3 + c)       = v0;
            *(float2*)(out + (size_t)(r + 8) * H3 + c) = v1;
        }
    }
}

// ===========================================================================
// Persistent loop: 256 CTAs (2/SM), tile 64x96, BK=64, 3-stage,
// double-buffered h/h2, ONE grid barrier per step.
// ===========================================================================
__global__ __launch_bounds__(256, 2)
void persist_loop(const float* __restrict__ ln_w,
                  const float* __restrict__ ln_b,
                  const float* __restrict__ b_hh,
                  float* __restrict__ out)
{
    extern __shared__ __align__(16) char dsm[];
    const uint32_t sbase = smem_u32(dsm);

    const int tid   = threadIdx.x;
    const int lane  = tid & 31;
    const int w     = tid >> 5;
    const int wr    = w & 1;        // 2 m-warps
    const int wc    = w >> 1;       // 4 n-warps
    const int qr    = lane >> 2;
    const int qc    = lane & 3;
    const int cid   = blockIdx.x;
    const int ntile = cid & 15;
    const int mtile = cid >> 4;
    const int row0  = mtile * LBM;
    const int col0  = ntile * LBN;
    const int hid0  = ntile * 32;

    // loader: 160 rows x 8 chunks = 1280 chunks = 256 thr x 5, no predication
    size_t  goff[5];
    uint32_t soff[5];
    bool isA[5];
    #pragma unroll
    for (int j = 0; j < 5; j++) {
        int idx = tid + 256 * j;
        int row = idx >> 3;
        int seg = (idx & 7) * 8;
        isA[j] = (row < LBM);
        if (row < LBM) goff[j] = (size_t)(row0 + row) * KTOT + seg;
        else           goff[j] = (size_t)(col0 + row - LBM) * KTOT + seg;
        soff[j] = (uint32_t)(row * LSA + seg) * 2;
    }

    // ldmatrix base offsets (bytes)
    uint32_t aoff[2], boff4, boff2;
    #pragma unroll
    for (int mi = 0; mi < 2; mi++)
        aoff[mi] = (uint32_t)((wr * 32 + mi * 16 + (lane & 7) + 8 * ((lane >> 3) & 1)) * LSA
                              + 8 * (lane >> 4)) * 2;
    boff4 = (uint32_t)((LBM + wc * 24 + (lane & 7) + 8 * (lane >> 4)) * LSA
                       + 8 * ((lane >> 3) & 1)) * 2;
    boff2 = (uint32_t)((LBM + wc * 24 + 16 + (lane & 7)) * LSA
                       + 8 * ((lane >> 3) & 1)) * 2;

    unsigned ph = 0;

    #pragma unroll 1
    for (int t = 0; t < TT; t++) {
        const int cur = t & 1;
        const int nxt = cur ^ 1;
        const float*         hcur  = g_h[cur];
        const __nv_bfloat16* h2cur = g_h2[cur];

        // ---------- LN emit: warps 0..3, one row each (4 rows per CTA) ----------
        if (w < 4) {
            int rown = cid * 4 + w;
            const float* hp = hcur + (size_t)rown * HD;
            float4 v[4];
            #pragma unroll
            for (int j = 0; j < 4; j++) v[j] = ((const float4*)hp)[lane + 32 * j];
            float s = 0.0f;
            #pragma unroll
            for (int j = 0; j < 4; j++) s += v[j].x + v[j].y + v[j].z + v[j].w;
            #pragma unroll
            for (int o = 16; o > 0; o >>= 1) s += __shfl_xor_sync(0xffffffffu, s, o);
            float mean = s * (1.0f / HD);
            float q = 0.0f;
            #pragma unroll
            for (int j = 0; j < 4; j++) {
                float a0 = v[j].x - mean, a1 = v[j].y - mean;
                float a2 = v[j].z - mean, a3 = v[j].w - mean;
                q += a0 * a0 + a1 * a1 + a2 * a2 + a3 * a3;
            }
            #pragma unroll
            for (int o = 16; o > 0; o >>= 1) q += __shfl_xor_sync(0xffffffffu, q, o);
            float rstd = rsqrtf(q * (1.0f / HD) + LN_EPS);
            float* orow = out + ((size_t)rown * TT + t) * HD;
            #pragma unroll
            for (int j = 0; j < 4; j++) {
                float4 lw = ((const float4*)ln_w)[lane + 32 * j];
                float4 lb = ((const float4*)ln_b)[lane + 32 * j];
                float4 o;
                o.x = (v[j].x - mean) * rstd * lw.x + lb.x;
                o.y = (v[j].y - mean) * rstd * lw.y + lb.y;
                o.z = (v[j].z - mean) * rstd * lw.z + lb.z;
                o.w = (v[j].w - mean) * rstd * lw.w + lb.w;
                ((float4*)orow)[lane + 32 * j] = o;
            }
        }
        if (t == TT - 1) break;

        // ---------- gh GEMM (64x96, K=1536, BK=64, 3-stage) ----------
        float acc[2][3][4];
        #pragma unroll
        for (int i = 0; i < 2; i++)
            #pragma unroll
            for (int j = 0; j < 3; j++)
                #pragma unroll
                for (int v = 0; v < 4; v++) acc[i][j][v] = 0.0f;

        #pragma unroll
        for (int s = 0; s < LNST - 1; s++) {
            uint32_t sb = sbase + s * LSTAGE;
            #pragma unroll
            for (int j = 0; j < 5; j++) {
                const __nv_bfloat16* p = (isA[j] ? h2cur : g_W2hh) + goff[j] + s * LBK;
                CP_ASYNC16(sb + soff[j], p);
            }
            CP_COMMIT();
        }

        #pragma unroll 1
        for (int kt = 0; kt < LKIT; kt++) {
            if (kt < LKIT - 1) CP_WAIT1();
            else               CP_WAIT0();
            __syncthreads();

            if (kt + LNST - 1 < LKIT) {
                int kc = kt + LNST - 1;
                uint32_t sb = sbase + (kc % LNST) * LSTAGE;
                #pragma unroll
                for (int j = 0; j < 5; j++) {
                    const __nv_bfloat16* p = (isA[j] ? h2cur : g_W2hh) + goff[j] + kc * LBK;
                    CP_ASYNC16(sb + soff[j], p);
                }
                CP_COMMIT();
            }

            uint32_t sst = sbase + (kt % LNST) * LSTAGE;
            #pragma unroll
            for (int ks = 0; ks < 4; ks++) {
                uint32_t kb2 = ks * 32;
                uint32_t af[2][4], bfa[4], bfb[2];
                #pragma unroll
                for (int mi = 0; mi < 2; mi++) ldsm4(af[mi], sst + aoff[mi] + kb2);
                ldsm4(bfa, sst + boff4 + kb2);
                ldsm2(bfb, sst + boff2 + kb2);
                #pragma unroll
                for (int ni = 0; ni < 3; ni++) {
                    uint32_t b0 = (ni < 2) ? bfa[ni * 2]     : bfb[0];
                    uint32_t b1 = (ni < 2) ? bfa[ni * 2 + 1] : bfb[1];
                    #pragma unroll
                    for (int mi = 0; mi < 2; mi++)
                        mma16816(acc[mi][ni], af[mi], b0, b1);
                }
            }
            __syncthreads();
        }

        // stage accumulators to smem
        float* sst = (float*)dsm;   // [64][97]
        #pragma unroll
        for (int mi = 0; mi < 2; mi++) {
            int r = wr * 32 + mi * 16 + qr;
            #pragma unroll
            for (int ni = 0; ni < 3; ni++) {
                int c = wc * 24 + ni * 8 + qc * 2;
                sst[r * SSTR + c]           = acc[mi][ni][0];
                sst[r * SSTR + c + 1]       = acc[mi][ni][1];
                sst[(r + 8) * SSTR + c]     = acc[mi][ni][2];
                sst[(r + 8) * SSTR + c + 1] = acc[mi][ni][3];
            }
        }
        __syncthreads();

        // GRU update: 64 rows x 32 hidden, always write nxt buffers
        {
            const unsigned char* actrow = g_active + (size_t)t * BQ;
            float*         hnb  = g_h[nxt];
            __nv_bfloat16* h2nb = g_h2[nxt];
            #pragma unroll
            for (int k = 0; k < (LBM * 32) / 256; k++) {
                int idx = tid + k * 256;
                int rl  = idx >> 5;
                int j   = idx & 31;
                int b   = row0 + rl;
                int hid = hid0 + j;

                float hold = hcur[(size_t)b * HD + hid];
                float hnew = hold;
                if (actrow[b]) {
                    float ghr = sst[rl * SSTR + 3 * j];
                    float ghz = sst[rl * SSTR + 3 * j + 1];
                    float ghn = sst[rl * SSTR + 3 * j + 2];
                    const float* gip = g_gi + ((size_t)t * BQ + b) * H3 + col0 + 3 * j;
                    float r = 1.0f / (1.0f + expf(-(gip[0] + ghr)));
                    float z = 1.0f / (1.0f + expf(-(gip[1] + ghz)));
                    float n = tanhf(gip[2] + r * (ghn + b_hh[1024 + hid]));
                    hnew = (1.0f - z) * n + z * hold;
                }
                hnb[(size_t)b * HD + hid] = hnew;
                __nv_bfloat16 hi = __float2bfloat16(hnew);
                __nv_bfloat16* h2row = h2nb + (size_t)b * KTOT;
                h2row[hid]          = hi;
                h2row[HD + hid]     = __float2bfloat16(hnew - __bfloat162float(hi));
                h2row[2 * HD + hid] = hi;
            }
        }
        grid_bar(++ph * PCTAS);
    }
}

// ===========================================================================
// prep kernels
// ===========================================================================
__global__ void prep_weights(const float* __restrict__ wih,
                             const float* __restrict__ whh)
{
    int n = blockIdx.x;
    int g = n >> 9, i = n & 511;
    int np = 3 * i + g;
    const float* src = (blockIdx.y == 0 ? wih : whh) + (size_t)n * HD;
    __nv_bfloat16* dst = (blockIdx.y == 0 ? g_W2ih : g_W2hh) + (size_t)np * KTOT;
    for (int k = threadIdx.x; k < HD; k += 128) {
        float x = src[k];
        __nv_bfloat16 hi = __float2bfloat16(x);
        float lo = x - __bfloat162float(hi);
        dst[k] = hi; dst[HD + k] = hi; dst[2 * HD + k] = __float2bfloat16(lo);
    }
}

__global__ void prep_bias_active(const float* __restrict__ b_ih,
                                 const float* __restrict__ b_hh,
                                 const int*   __restrict__ actions,
                                 const int*   __restrict__ stop_idx)
{
    int x = blockIdx.x * 256 + threadIdx.x;
    if (x == 0) g_barctr = 0;
    if (x < H3) {
        int g = x >> 9, i = x & 511;
        g_bsum[3 * i + g] = b_ih[x] + (g < 2 ? b_hh[x] : 0.0f);
    }
    if (x < BQ) {
        int b = x;
        int si = stop_idx[b];
        bool done = false;
        for (int t = 0; t < TT; t++) {
            int a = actions[b * TT + t];
            bool is_stop = (a == si) || (a < 0);
            g_active[t * BQ + b] = (!done && !is_stop) ? 1 : 0;
            done = done || is_stop;
        }
    }
}

__global__ void prep_agi(const int* __restrict__ actions,
                         const float* __restrict__ edge_tokens, int E)
{
    int m = blockIdx.x;
    int t = m >> 10, b = m & (BQ - 1);
    int a = actions[b * TT + t];
    a = a < 0 ? 0 : (a >= E ? E - 1 : a);
    const float* src = edge_tokens + (size_t)a * HD;
    __nv_bfloat16* dst = g_Agi + (size_t)m * KTOT;
    for (int k = threadIdx.x; k < HD; k += 128) {
        float x = src[k];
        __nv_bfloat16 hi = __float2bfloat16(x);
        float lo = x - __bfloat162float(hi);
        dst[k] = hi; dst[HD + k] = __float2bfloat16(lo); dst[2 * HD + k] = hi;
    }
}

// ===========================================================================
// init
// ===========================================================================
__device__ __forceinline__ float block_sum_256(float v, float* red)
{
    int lane = threadIdx.x & 31, w = threadIdx.x >> 5;
    #pragma unroll
    for (int o = 16; o > 0; o >>= 1) v += __shfl_xor_sync(0xffffffffu, v, o);
    if (lane == 0) red[w] = v;
    __syncthreads();
    if (w == 0) {
        float x = (lane < 8) ? red[lane] : 0.0f;
        #pragma unroll
        for (int o = 4; o > 0; o >>= 1) x += __shfl_xor_sync(0xffffffffu, x, o);
        if (lane == 0) red[0] = x;
    }
    __syncthreads();
    float r = red[0];
    __syncthreads();
    return r;
}

__global__ void init_kernel(const float* __restrict__ question,
                            const float* __restrict__ node_tokens,
                            const int*   __restrict__ locals,
                            const int*   __restrict__ ptr,
                            const float* __restrict__ ln_w,
                            const float* __restrict__ ln_b)
{
    __shared__ float red[8];
    int b = blockIdx.x, tid = threadIdx.x;
    int p0 = ptr[b], p1 = ptr[b + 1];
    int cnt = p1 - p0;
    float inv = 1.0f / (float)(cnt > 0 ? cnt : 1);

    float s0 = 0.0f, s1 = 0.0f;
    for (int j = p0; j < p1; j++) {
        const float* nrow = node_tokens + (size_t)locals[j] * HD;
        s0 += nrow[tid]; s1 += nrow[tid + 256];
    }
    const float* q = question + (size_t)b * HD;
    float x0 = q[tid] + s0 * inv, x1 = q[tid + 256] + s1 * inv;

    float mean = block_sum_256(x0 + x1, red) * (1.0f / HD);
    float d0 = x0 - mean, d1 = x1 - mean;
    float var = block_sum_256(d0 * d0 + d1 * d1, red) * (1.0f / HD);
    float rstd = rsqrtf(var + LN_EPS);

    float v0 = d0 * rstd * ln_w[tid] + ln_b[tid];
    float v1 = d1 * rstd * ln_w[tid + 256] + ln_b[tid + 256];
    float* hrow = g_h[0] + (size_t)b * HD;
    hrow[tid] = v0; hrow[tid + 256] = v1;

    __nv_bfloat16* h2row = g_h2[0] + (size_t)b * KTOT;
    __nv_bfloat16 h0 = __float2bfloat16(v0);
    h2row[tid]            = h0;
    h2row[HD + tid]       = __float2bfloat16(v0 - __bfloat162float(h0));
    h2row[2 * HD + tid]   = h0;
    __nv_bfloat16 h1 = __float2bfloat16(v1);
    h2row[tid + 256]          = h1;
    h2row[HD + tid + 256]     = __float2bfloat16(v1 - __bfloat162float(h1));
    h2row[2 * HD + tid + 256] = h1;
}

// ===========================================================================
// launch
// ===========================================================================
extern "C" void kernel_launch(void* const* d_in, const int* in_sizes, int n_in,
                              void* d_out, int out_size)
{
    const int*   actions      = (const int*)  d_in[0];
    const float* edge_tokens  = (const float*)d_in[1];
    const int*   stop_indices = (const int*)  d_in[2];
    const float* question     = (const float*)d_in[3];
    const float* node_tokens  = (const float*)d_in[4];
    const int*   start_locals = (const int*)  d_in[5];
    const int*   start_ptr    = (const int*)  d_in[6];
    const float* w_ih         = (const float*)d_in[7];
    const float* w_hh         = (const float*)d_in[8];
    const float* b_ih         = (const float*)d_in[9];
    const float* b_hh         = (const float*)d_in[10];
    const float* ln_w         = (const float*)d_in[11];
    const float* ln_b         = (const float*)d_in[12];
    float* out = (float*)d_out;
    const int E = in_sizes[1] / HD;

    void *pAgi, *pWih, *pGi, *pBsum;
    cudaGetSymbolAddress(&pAgi, g_Agi);
    cudaGetSymbolAddress(&pWih, g_W2ih);
    cudaGetSymbolAddress(&pGi,  g_gi);
    cudaGetSymbolAddress(&pBsum, g_bsum);

    cudaFuncSetAttribute(gemm_big, cudaFuncAttributeMaxDynamicSharedMemorySize, BIG_SMEM);
    cudaFuncSetAttribute(persist_loop, cudaFuncAttributeMaxDynamicSharedMemorySize, LSMEM);

    prep_weights<<<dim3(H3, 2), 128>>>(w_ih, w_hh);
    prep_bias_active<<<(H3 + 255) / 256, 256>>>(b_ih, b_hh, actions, stop_indices);
    prep_agi<<<MGI, 128>>>(actions, edge_tokens, E);
    init_kernel<<<BQ, 256>>>(question, node_tokens, start_locals, start_ptr, ln_w, ln_b);

    gemm_big<<<dim3(H3 / BBN, MGI / BBM), 256, BIG_SMEM>>>(
        (const __nv_bfloat16*)pAgi, (const __nv_bfloat16*)pWih,
        (const float*)pBsum, (float*)pGi);

    persist_loop<<<PCTAS, 256, LSMEM>>>(ln_w, ln_b, b_hh, out);
}

// round 7
// speedup vs baseline: 1.4204x; 1.0498x over previous
#include <cuda_runtime.h>
#include <cuda_bf16.h>
#include <math.h>
#include <stdint.h>

// ---------------- problem dims ----------------
#define BQ   1024
#define TT   64
#define HD   512
#define H3   1536
#define MGI  (BQ * TT)
#define KTOT 1536               // K' = 3 * 512 (bf16x3 split folded into K)
#define LN_EPS 1e-5f

// ---- big (gi) GEMM tiling ----
#define BK 32
#define KITERS (KTOT / BK)      // 48
#define SA 40
#define NSTAGE 4
#define BBM 128
#define BBN 128
#define BSTAGE ((BBM + BBN) * SA * 2)
#define BIG_SMEM (NSTAGE * BSTAGE)      // 81920

// ---- persistent loop tiling: 64x96, BK=64, 4 stages, 256 CTAs (2/SM) ----
#define LBM 64
#define LBN 96
#define LBK 64
#define LSA 72
#define LKIT (KTOT / LBK)               // 24
#define LROWS (LBM + LBN)               // 160
#define LSTAGE (LROWS * LSA * 2)        // 23040
#define LNST 4
#define LSMEM (LNST * LSTAGE)           // 92160
#define PCTAS 256
#define SSTR 97

// ---------------- device scratch ----------------
__device__ __nv_bfloat16 g_Agi[(size_t)MGI * KTOT];
__device__ float         g_gi [(size_t)MGI * H3];     // gate-interleaved cols, biases folded
__device__ __nv_bfloat16 g_W2ih[(size_t)H3 * KTOT];   // gate-interleaved rows, [Wh|Wh|Wl]
__device__ __nv_bfloat16 g_W2hh[(size_t)H3 * KTOT];
__device__ __nv_bfloat16 g_h2[2][(size_t)BQ * KTOT];  // ping-pong [hh | hl | hh]
__device__ float         g_h [2][(size_t)BQ * HD];
__device__ float         g_bsum[H3];
__device__ int           g_perm[BQ];                  // new index -> orig row
__device__ int           g_nact[TT];                  // active count per step
__device__ unsigned int  g_barctr;

// ---------------- helpers ----------------
__device__ __forceinline__ uint32_t smem_u32(const void* p) {
    uint32_t a;
    asm("{ .reg .u64 t; cvta.to.shared.u64 t, %1; cvt.u32.u64 %0, t; }" : "=r"(a) : "l"(p));
    return a;
}
#define CP_ASYNC16(dst, src) \
    asm volatile("cp.async.cg.shared.global [%0], [%1], 16;" :: "r"(dst), "l"(src))
#define CP_COMMIT() asm volatile("cp.async.commit_group;" ::: "memory")
#define CP_WAIT0()  asm volatile("cp.async.wait_group 0;" ::: "memory")
#define CP_WAIT1()  asm volatile("cp.async.wait_group 1;" ::: "memory")
#define CP_WAIT2()  asm volatile("cp.async.wait_group 2;" ::: "memory")

__device__ __forceinline__ void mma16816(float* c, const uint32_t* a,
                                         uint32_t b0, uint32_t b1)
{
    asm volatile(
        "mma.sync.aligned.m16n8k16.row.col.f32.bf16.bf16.f32 "
        "{%0,%1,%2,%3}, {%4,%5,%6,%7}, {%8,%9}, {%0,%1,%2,%3};"
        : "+f"(c[0]), "+f"(c[1]), "+f"(c[2]), "+f"(c[3])
        : "r"(a[0]), "r"(a[1]), "r"(a[2]), "r"(a[3]), "r"(b0), "r"(b1));
}
__device__ __forceinline__ void ldsm4(uint32_t* r, uint32_t addr) {
    asm volatile("ldmatrix.sync.aligned.m8n8.x4.shared.b16 {%0,%1,%2,%3}, [%4];"
                 : "=r"(r[0]), "=r"(r[1]), "=r"(r[2]), "=r"(r[3]) : "r"(addr));
}
__device__ __forceinline__ void ldsm2(uint32_t* r, uint32_t addr) {
    asm volatile("ldmatrix.sync.aligned.m8n8.x2.shared.b16 {%0,%1}, [%2];"
                 : "=r"(r[0]), "=r"(r[1]) : "r"(addr));
}
__device__ __forceinline__ unsigned ld_acq(unsigned* p) {
    unsigned v;
    asm volatile("ld.acquire.gpu.u32 %0, [%1];" : "=r"(v) : "l"(p));
    return v;
}
__device__ __forceinline__ void grid_bar(unsigned target) {
    __syncthreads();
    if (threadIdx.x == 0) {
        __threadfence();
        atomicAdd(&g_barctr, 1u);
        while (ld_acq(&g_barctr) < target) {}
        __threadfence();
    }
    __syncthreads();
}

// ===========================================================================
// sort rows by stop length (descending) -> g_perm, g_nact. 1 CTA, 1024 thr.
// ===========================================================================
__global__ void sort_kernel(const int* __restrict__ actions,
                            const int* __restrict__ stop_idx)
{
    __shared__ int counts[TT + 1];
    __shared__ int start[TT + 1];
    int tid = threadIdx.x;
    if (tid <= TT) counts[tid] = 0;
    __syncthreads();

    int si = stop_idx[tid];
    int sl = TT;
    for (int t = 0; t < TT; t++) {
        int a = actions[tid * TT + t];
        if (a < 0 || a == si) { sl = t; break; }
    }
    atomicAdd(&counts[sl], 1);
    __syncthreads();
    if (tid == 0) {
        int acc = 0;
        for (int s = TT; s >= 0; s--) { start[s] = acc; acc += counts[s]; }
        for (int t = 0; t < TT; t++) g_nact[t] = start[t];  // #rows with sl > t
        g_barctr = 0;
    }
    __syncthreads();
    int pos = atomicAdd(&start[sl], 1);
    g_perm[pos] = tid;
}

// ===========================================================================
// Big GEMM (gi): out[M, H3] = A x B^T + bias ; tile 128x128
// ===========================================================================
__global__ __launch_bounds__(256)
void gemm_big(const __nv_bfloat16* __restrict__ A,
              const __nv_bfloat16* __restrict__ B,
              const float* __restrict__ bias,
              float* __restrict__ out)
{
    const int col0 = blockIdx.x * BBN;
    const int row0 = blockIdx.y * BBM;
    // skip tiles whose gi rows are never consumed (inactive suffix at step t)
    if ((row0 & 1023) >= g_nact[row0 >> 10]) return;

    extern __shared__ __align__(16) char dsm[];
    const uint32_t sbase = smem_u32(dsm);

    const int tid  = threadIdx.x;
    const int lane = tid & 31;
    const int w    = tid >> 5;
    const int wr   = w & 1;
    const int wc   = w >> 1;
    const int qr   = lane >> 2;
    const int qc   = lane & 3;

    const __nv_bfloat16* srcp[4];
    uint32_t soff[4];
    #pragma unroll
    for (int j = 0; j < 4; j++) {
        int idx  = tid + 256 * j;
        int arow = idx >> 2;
        int seg  = (idx & 3) * 8;
        if (arow < BBM) {
            srcp[j] = A + (size_t)(row0 + arow) * KTOT + seg;
            soff[j] = (uint32_t)(arow * SA + seg) * 2;
        } else {
            int brow = arow - BBM;
            srcp[j] = B + (size_t)(col0 + brow) * KTOT + seg;
            soff[j] = (uint32_t)((BBM + brow) * SA + seg) * 2;
        }
    }

    uint32_t aoff[4], boff[2];
    #pragma unroll
    for (int mi = 0; mi < 4; mi++)
        aoff[mi] = (uint32_t)((wr * 64 + mi * 16 + (lane & 7) + 8 * ((lane >> 3) & 1)) * SA
                              + 8 * (lane >> 4)) * 2;
    #pragma unroll
    for (int p = 0; p < 2; p++)
        boff[p] = (uint32_t)((BBM + wc * 32 + p * 16 + (lane & 7) + 8 * (lane >> 4)) * SA
                             + 8 * ((lane >> 3) & 1)) * 2;

    float acc[4][4][4];
    #pragma unroll
    for (int i = 0; i < 4; i++)
        #pragma unroll
        for (int j = 0; j < 4; j++)
            #pragma unroll
            for (int v = 0; v < 4; v++) acc[i][j][v] = 0.0f;

    #pragma unroll
    for (int s = 0; s < NSTAGE - 1; s++) {
        uint32_t sb = sbase + s * BSTAGE;
        #pragma unroll
        for (int j = 0; j < 4; j++) CP_ASYNC16(sb + soff[j], srcp[j] + s * BK);
        CP_COMMIT();
    }

    #pragma unroll 1
    for (int kt = 0; kt < KITERS; kt++) {
        if (kt < KITERS - 2)       CP_WAIT2();
        else if (kt == KITERS - 2) CP_WAIT1();
        else                       CP_WAIT0();
        __syncthreads();

        if (kt + NSTAGE - 1 < KITERS) {
            int kc = kt + NSTAGE - 1;
            uint32_t sb = sbase + (kc & (NSTAGE - 1)) * BSTAGE;
            #pragma unroll
            for (int j = 0; j < 4; j++) CP_ASYNC16(sb + soff[j], srcp[j] + kc * BK);
            CP_COMMIT();
        }

        uint32_t sst = sbase + (kt & (NSTAGE - 1)) * BSTAGE;
        #pragma unroll
        for (int ks = 0; ks < 2; ks++) {
            uint32_t kb2 = ks * 32;
            uint32_t af[4][4], bf[2][4];
            #pragma unroll
            for (int mi = 0; mi < 4; mi++) ldsm4(af[mi], sst + aoff[mi] + kb2);
            #pragma unroll
            for (int p = 0; p < 2; p++)    ldsm4(bf[p], sst + boff[p] + kb2);
            #pragma unroll
            for (int ni = 0; ni < 4; ni++) {
                uint32_t b0 = bf[ni >> 1][(ni & 1) * 2];
                uint32_t b1 = bf[ni >> 1][(ni & 1) * 2 + 1];
                #pragma unroll
                for (int mi = 0; mi < 4; mi++)
                    mma16816(acc[mi][ni], af[mi], b0, b1);
            }
        }
        __syncthreads();
    }

    #pragma unroll
    for (int mi = 0; mi < 4; mi++) {
        int r = row0 + wr * 64 + mi * 16 + qr;
        #pragma unroll
        for (int ni = 0; ni < 4; ni++) {
            int c = col0 + wc * 32 + ni * 8 + qc * 2;
            float2 bv = *(const float2*)(bias + c);
            float2 v0 = make_float2(acc[mi][ni][0] + bv.x, acc[mi][ni][1] + bv.y);
            float2 v1 = make_float2(acc[mi][ni][2] + bv.x, acc[mi][ni][3] + bv.y);
            *(float2*)(out + (size_t)r * H3 + c)       = v0;
            *(float2*)(out + (size_t)(r + 8) * H3 + c) = v1;
        }
    }
}

// ===========================================================================
// Persistent loop: 256 CTAs (2/SM), tile 64x96, BK=64, 4-stage,
// sorted rows -> active prefix; inactive m-tiles skip the GEMM entirely.
// ===========================================================================
__global__ __launch_bounds__(256, 2)
void persist_loop(const float* __restrict__ ln_w,
                  const float* __restrict__ ln_b,
                  const float* __restrict__ b_hh,
                  float* __restrict__ out)
{
    extern __shared__ __align__(16) char dsm[];
    const uint32_t sbase = smem_u32(dsm);

    const int tid   = threadIdx.x;
    const int lane  = tid & 31;
    const int w     = tid >> 5;
    const int wr    = w & 1;
    const int wc    = w >> 1;
    const int qr    = lane >> 2;
    const int qc    = lane & 3;
    const int cid   = blockIdx.x;
    const int ntile = cid & 15;
    const int mtile = cid >> 4;
    const int row0  = mtile * LBM;
    const int col0  = ntile * LBN;
    const int hid0  = ntile * 32;

    // orig row for this thread's LN row (constant across steps)
    int orig_ln = 0;
    if (w < 4) orig_ln = g_perm[cid * 4 + w];

    // loader mapping: 160 rows x 8 chunks = 1280 = 256 x 5
    size_t  goff[5];
    uint32_t soff[5];
    bool isA[5];
    #pragma unroll
    for (int j = 0; j < 5; j++) {
        int idx = tid + 256 * j;
        int row = idx >> 3;
        int seg = (idx & 7) * 8;
        isA[j] = (row < LBM);
        if (row < LBM) goff[j] = (size_t)(row0 + row) * KTOT + seg;
        else           goff[j] = (size_t)(col0 + row - LBM) * KTOT + seg;
        soff[j] = (uint32_t)(row * LSA + seg) * 2;
    }

    uint32_t aoff[2], boff4, boff2;
    #pragma unroll
    for (int mi = 0; mi < 2; mi++)
        aoff[mi] = (uint32_t)((wr * 32 + mi * 16 + (lane & 7) + 8 * ((lane >> 3) & 1)) * LSA
                              + 8 * (lane >> 4)) * 2;
    boff4 = (uint32_t)((LBM + wc * 24 + (lane & 7) + 8 * (lane >> 4)) * LSA
                       + 8 * ((lane >> 3) & 1)) * 2;
    boff2 = (uint32_t)((LBM + wc * 24 + 16 + (lane & 7)) * LSA
                       + 8 * ((lane >> 3) & 1)) * 2;

    unsigned ph = 0;

    #pragma unroll 1
    for (int t = 0; t < TT; t++) {
        const int cur = t & 1;
        const int nxt = cur ^ 1;
        const float*         hcur  = g_h[cur];
        const __nv_bfloat16* h2cur = g_h2[cur];
        const int nact = g_nact[t];

        // ---------- LN emit: warps 0..3, one row each ----------
        if (w < 4) {
            int rown = cid * 4 + w;
            const float* hp = hcur + (size_t)rown * HD;
            float4 v[4];
            #pragma unroll
            for (int j = 0; j < 4; j++) v[j] = ((const float4*)hp)[lane + 32 * j];
            float s = 0.0f;
            #pragma unroll
            for (int j = 0; j < 4; j++) s += v[j].x + v[j].y + v[j].z + v[j].w;
            #pragma unroll
            for (int o = 16; o > 0; o >>= 1) s += __shfl_xor_sync(0xffffffffu, s, o);
            float mean = s * (1.0f / HD);
            float q = 0.0f;
            #pragma unroll
            for (int j = 0; j < 4; j++) {
                float a0 = v[j].x - mean, a1 = v[j].y - mean;
                float a2 = v[j].z - mean, a3 = v[j].w - mean;
                q += a0 * a0 + a1 * a1 + a2 * a2 + a3 * a3;
            }
            #pragma unroll
            for (int o = 16; o > 0; o >>= 1) q += __shfl_xor_sync(0xffffffffu, q, o);
            float rstd = rsqrtf(q * (1.0f / HD) + LN_EPS);
            float* orow = out + ((size_t)orig_ln * TT + t) * HD;
            #pragma unroll
            for (int j = 0; j < 4; j++) {
                float4 lw = ((const float4*)ln_w)[lane + 32 * j];
                float4 lb = ((const float4*)ln_b)[lane + 32 * j];
                float4 o;
                o.x = (v[j].x - mean) * rstd * lw.x + lb.x;
                o.y = (v[j].y - mean) * rstd * lw.y + lb.y;
                o.z = (v[j].z - mean) * rstd * lw.z + lb.z;
                o.w = (v[j].w - mean) * rstd * lw.w + lb.w;
                ((float4*)orow)[lane + 32 * j] = o;
            }
        }
        if (t == TT - 1) break;

        const bool tile_active = (row0 < nact);
        float* sst = (float*)dsm;   // staging alias

        if (tile_active) {
            // ---------- gh GEMM (64x96, K=1536, BK=64, 4-stage) ----------
            float acc[2][3][4];
            #pragma unroll
            for (int i = 0; i < 2; i++)
                #pragma unroll
                for (int j = 0; j < 3; j++)
                    #pragma unroll
                    for (int v = 0; v < 4; v++) acc[i][j][v] = 0.0f;

            #pragma unroll
            for (int s = 0; s < LNST - 1; s++) {
                uint32_t sb = sbase + s * LSTAGE;
                #pragma unroll
                for (int j = 0; j < 5; j++) {
                    const __nv_bfloat16* p = (isA[j] ? h2cur : g_W2hh) + goff[j] + s * LBK;
                    CP_ASYNC16(sb + soff[j], p);
                }
                CP_COMMIT();
            }

            #pragma unroll 1
            for (int kt = 0; kt < LKIT; kt++) {
                if (kt < LKIT - 2)       CP_WAIT2();
                else if (kt == LKIT - 2) CP_WAIT1();
                else                     CP_WAIT0();
                __syncthreads();

                if (kt + LNST - 1 < LKIT) {
                    int kc = kt + LNST - 1;
                    uint32_t sb = sbase + (kc & (LNST - 1)) * LSTAGE;
                    #pragma unroll
                    for (int j = 0; j < 5; j++) {
                        const __nv_bfloat16* p = (isA[j] ? h2cur : g_W2hh) + goff[j] + kc * LBK;
                        CP_ASYNC16(sb + soff[j], p);
                    }
                    CP_COMMIT();
                }

                uint32_t sstage = sbase + (kt & (LNST - 1)) * LSTAGE;
                #pragma unroll
                for (int ks = 0; ks < 4; ks++) {
                    uint32_t kb2 = ks * 32;
                    uint32_t af[2][4], bfa[4], bfb[2];
                    #pragma unroll
                    for (int mi = 0; mi < 2; mi++) ldsm4(af[mi], sstage + aoff[mi] + kb2);
                    ldsm4(bfa, sstage + boff4 + kb2);
                    ldsm2(bfb, sstage + boff2 + kb2);
                    #pragma unroll
                    for (int ni = 0; ni < 3; ni++) {
                        uint32_t b0 = (ni < 2) ? bfa[ni * 2]     : bfb[0];
                        uint32_t b1 = (ni < 2) ? bfa[ni * 2 + 1] : bfb[1];
                        #pragma unroll
                        for (int mi = 0; mi < 2; mi++)
                            mma16816(acc[mi][ni], af[mi], b0, b1);
                    }
                }
                __syncthreads();
            }

            // stage accumulators to smem
            #pragma unroll
            for (int mi = 0; mi < 2; mi++) {
                int r = wr * 32 + mi * 16 + qr;
                #pragma unroll
                for (int ni = 0; ni < 3; ni++) {
                    int c = wc * 24 + ni * 8 + qc * 2;
                    sst[r * SSTR + c]           = acc[mi][ni][0];
                    sst[r * SSTR + c + 1]       = acc[mi][ni][1];
                    sst[(r + 8) * SSTR + c]     = acc[mi][ni][2];
                    sst[(r + 8) * SSTR + c + 1] = acc[mi][ni][3];
                }
            }
            __syncthreads();
        }

        // ---------- GRU update / copy ----------
        {
            float*         hnb  = g_h[nxt];
            __nv_bfloat16* h2nb = g_h2[nxt];
            #pragma unroll
            for (int k = 0; k < (LBM * 32) / 256; k++) {
                int idx = tid + k * 256;
                int rl  = idx >> 5;
                int j   = idx & 31;
                int b   = row0 + rl;
                int hid = hid0 + j;

                float hold = hcur[(size_t)b * HD + hid];
                float hnew = hold;
                if (b < nact) {
                    float ghr = sst[rl * SSTR + 3 * j];
                    float ghz = sst[rl * SSTR + 3 * j + 1];
                    float ghn = sst[rl * SSTR + 3 * j + 2];
                    const float* gip = g_gi + ((size_t)t * BQ + b) * H3 + col0 + 3 * j;
                    float r = 1.0f / (1.0f + expf(-(gip[0] + ghr)));
                    float z = 1.0f / (1.0f + expf(-(gip[1] + ghz)));
                    float n = tanhf(gip[2] + r * (ghn + b_hh[1024 + hid]));
                    hnew = (1.0f - z) * n + z * hold;
                }
                hnb[(size_t)b * HD + hid] = hnew;
                __nv_bfloat16 hi = __float2bfloat16(hnew);
                __nv_bfloat16* h2row = h2nb + (size_t)b * KTOT;
                h2row[hid]          = hi;
                h2row[HD + hid]     = __float2bfloat16(hnew - __bfloat162float(hi));
                h2row[2 * HD + hid] = hi;
            }
        }
        grid_bar(++ph * PCTAS);
    }
}

// ===========================================================================
// prep kernels
// ===========================================================================
__global__ void prep_weights(const float* __restrict__ wih,
                             const float* __restrict__ whh)
{
    int n = blockIdx.x;
    int g = n >> 9, i = n & 511;
    int np = 3 * i + g;
    const float* src = (blockIdx.y == 0 ? wih : whh) + (size_t)n * HD;
    __nv_bfloat16* dst = (blockIdx.y == 0 ? g_W2ih : g_W2hh) + (size_t)np * KTOT;
    for (int k = threadIdx.x; k < HD; k += 128) {
        float x = src[k];
        __nv_bfloat16 hi = __float2bfloat16(x);
        float lo = x - __bfloat162float(hi);
        dst[k] = hi; dst[HD + k] = hi; dst[2 * HD + k] = __float2bfloat16(lo);
    }
}

__global__ void prep_bias(const float* __restrict__ b_ih,
                          const float* __restrict__ b_hh)
{
    int x = blockIdx.x * 256 + threadIdx.x;
    if (x < H3) {
        int g = x >> 9, i = x & 511;
        g_bsum[3 * i + g] = b_ih[x] + (g < 2 ? b_hh[x] : 0.0f);
    }
}

__global__ void prep_agi(const int* __restrict__ actions,
                         const float* __restrict__ edge_tokens, int E)
{
    int m = blockIdx.x;
    int t = m >> 10, nb = m & (BQ - 1);
    if (nb >= g_nact[t]) return;            // row never consumed
    int b = g_perm[nb];
    int a = actions[b * TT + t];
    a = a < 0 ? 0 : (a >= E ? E - 1 : a);
    const float* src = edge_tokens + (size_t)a * HD;
    __nv_bfloat16* dst = g_Agi + (size_t)m * KTOT;
    for (int k = threadIdx.x; k < HD; k += 128) {
        float x = src[k];
        __nv_bfloat16 hi = __float2bfloat16(x);
        float lo = x - __bfloat162float(hi);
        dst[k] = hi; dst[HD + k] = __float2bfloat16(lo); dst[2 * HD + k] = hi;
    }
}

// ===========================================================================
// init
// ===========================================================================
__device__ __forceinline__ float block_sum_256(float v, float* red)
{
    int lane = threadIdx.x & 31, w = threadIdx.x >> 5;
    #pragma unroll
    for (int o = 16; o > 0; o >>= 1) v += __shfl_xor_sync(0xffffffffu, v, o);
    if (lane == 0) red[w] = v;
    __syncthreads();
    if (w == 0) {
        float x = (lane < 8) ? red[lane] : 0.0f;
        #pragma unroll
        for (int o = 4; o > 0; o >>= 1) x += __shfl_xor_sync(0xffffffffu, x, o);
        if (lane == 0) red[0] = x;
    }
    __syncthreads();
    float r = red[0];
    __syncthreads();
    return r;
}

__global__ void init_kernel(const float* __restrict__ question,
                            const float* __restrict__ node_tokens,
                            const int*   __restrict__ locals,
                            const int*   __restrict__ ptr,
                            const float* __restrict__ ln_w,
                            const float* __restrict__ ln_b)
{
    __shared__ float red[8];
    int nb = blockIdx.x, tid = threadIdx.x;
    int b = g_perm[nb];
    int p0 = ptr[b], p1 = ptr[b + 1];
    int cnt = p1 - p0;
    float inv = 1.0f / (float)(cnt > 0 ? cnt : 1);

    float s0 = 0.0f, s1 = 0.0f;
    for (int j = p0; j < p1; j++) {
        const float* nrow = node_tokens + (size_t)locals[j] * HD;
        s0 += nrow[tid]; s1 += nrow[tid + 256];
    }
    const float* q = question + (size_t)b * HD;
    float x0 = q[tid] + s0 * inv, x1 = q[tid + 256] + s1 * inv;

    float mean = block_sum_256(x0 + x1, red) * (1.0f / HD);
    float d0 = x0 - mean, d1 = x1 - mean;
    float var = block_sum_256(d0 * d0 + d1 * d1, red) * (1.0f / HD);
    float rstd = rsqrtf(var + LN_EPS);

    float v0 = d0 * rstd * ln_w[tid] + ln_b[tid];
    float v1 = d1 * rstd * ln_w[tid + 256] + ln_b[tid + 256];
    float* hrow = g_h[0] + (size_t)nb * HD;
    hrow[tid] = v0; hrow[tid + 256] = v1;

    __nv_bfloat16* h2row = g_h2[0] + (size_t)nb * KTOT;
    __nv_bfloat16 h0 = __float2bfloat16(v0);
    h2row[tid]            = h0;
    h2row[HD + tid]       = __float2bfloat16(v0 - __bfloat162float(h0));
    h2row[2 * HD + tid]   = h0;
    __nv_bfloat16 h1 = __float2bfloat16(v1);
    h2row[tid + 256]          = h1;
    h2row[HD + tid + 256]     = __float2bfloat16(v1 - __bfloat162float(h1));
    h2row[2 * HD + tid + 256] = h1;
}

// ===========================================================================
// launch
// ===========================================================================
extern "C" void kernel_launch(void* const* d_in, const int* in_sizes, int n_in,
                              void* d_out, int out_size)
{
    const int*   actions      = (const int*)  d_in[0];
    const float* edge_tokens  = (const float*)d_in[1];
    const int*   stop_indices = (const int*)  d_in[2];
    const float* question     = (const float*)d_in[3];
    const float* node_tokens  = (const float*)d_in[4];
    const int*   start_locals = (const int*)  d_in[5];
    const int*   start_ptr    = (const int*)  d_in[6];
    const float* w_ih         = (const float*)d_in[7];
    const float* w_hh         = (const float*)d_in[8];
    const float* b_ih         = (const float*)d_in[9];
    const float* b_hh         = (const float*)d_in[10];
    const float* ln_w         = (const float*)d_in[11];
    const float* ln_b         = (const float*)d_in[12];
    float* out = (float*)d_out;
    const int E = in_sizes[1] / HD;

    void *pAgi, *pWih, *pGi, *pBsum;
    cudaGetSymbolAddress(&pAgi, g_Agi);
    cudaGetSymbolAddress(&pWih, g_W2ih);
    cudaGetSymbolAddress(&pGi,  g_gi);
    cudaGetSymbolAddress(&pBsum, g_bsum);

    cudaFuncSetAttribute(gemm_big, cudaFuncAttributeMaxDynamicSharedMemorySize, BIG_SMEM);
    cudaFuncSetAttribute(persist_loop, cudaFuncAttributeMaxDynamicSharedMemorySize, LSMEM);

    prep_weights<<<dim3(H3, 2), 128>>>(w_ih, w_hh);
    prep_bias<<<(H3 + 255) / 256, 256>>>(b_ih, b_hh);
    sort_kernel<<<1, 1024>>>(actions, stop_indices);
    prep_agi<<<MGI, 128>>>(actions, edge_tokens, E);
    init_kernel<<<BQ, 256>>>(question, node_tokens, start_locals, start_ptr, ln_w, ln_b);

    gemm_big<<<dim3(H3 / BBN, MGI / BBM), 256, BIG_SMEM>>>(
        (const __nv_bfloat16*)pAgi, (const __nv_bfloat16*)pWih,
        (const float*)pBsum, (float*)pGi);

    persist_loop<<<PCTAS, 256, LSMEM>>>(ln_w, ln_b, b_hh, out);
}

// round 8
// speedup vs baseline: 1.8679x; 1.3151x over previous
#include <cuda_runtime.h>
#include <cuda_fp16.h>
#include <math.h>
#include <stdint.h>

// ---------------- problem dims ----------------
#define BQ   1024
#define TT   64
#define HD   512
#define H3   1536
#define MGI  (BQ * TT)
#define KTOT 1024               // K' = 2 * 512 (fp16x2 split of A; W=[Wh|Wh])
#define LN_EPS 1e-5f

// ---- big (gi) GEMM tiling ----
#define BK 32
#define KITERS (KTOT / BK)      // 32
#define SA 40
#define NSTAGE 4
#define BBM 128
#define BBN 128
#define BSTAGE ((BBM + BBN) * SA * 2)
#define BIG_SMEM (NSTAGE * BSTAGE)      // 81920

// ---- persistent loop tiling: 64x96, BK=64, 4 stages, 256 CTAs (2/SM) ----
#define LBM 64
#define LBN 96
#define LBK 64
#define LSA 72
#define LKIT (KTOT / LBK)               // 16
#define LROWS (LBM + LBN)               // 160
#define LSTAGE (LROWS * LSA * 2)        // 23040
#define LNST 4
#define LSMEM (LNST * LSTAGE)           // 92160
#define PCTAS 256
#define SSTR 97

// ---------------- device scratch ----------------
__device__ __half g_Agi[(size_t)MGI * KTOT];
__device__ float  g_gi [(size_t)MGI * H3];     // gate-interleaved cols, biases folded
__device__ __half g_W2ih[(size_t)H3 * KTOT];   // gate-interleaved rows, [Wh|Wh]
__device__ __half g_W2hh[(size_t)H3 * KTOT];
__device__ __half g_h2[2][(size_t)BQ * KTOT];  // ping-pong [Ah | Al]
__device__ float  g_h [2][(size_t)BQ * HD];
__device__ float  g_bsum[H3];
__device__ int    g_perm[BQ];                  // new index -> orig row
__device__ int    g_sl[BQ];                    // stop length per new index
__device__ int    g_nact[TT];                  // active count per step
__device__ unsigned int g_barctr;

// ---------------- helpers ----------------
__device__ __forceinline__ uint32_t smem_u32(const void* p) {
    uint32_t a;
    asm("{ .reg .u64 t; cvta.to.shared.u64 t, %1; cvt.u32.u64 %0, t; }" : "=r"(a) : "l"(p));
    return a;
}
#define CP_ASYNC16(dst, src) \
    asm volatile("cp.async.cg.shared.global [%0], [%1], 16;" :: "r"(dst), "l"(src))
#define CP_COMMIT() asm volatile("cp.async.commit_group;" ::: "memory")
#define CP_WAIT0()  asm volatile("cp.async.wait_group 0;" ::: "memory")
#define CP_WAIT1()  asm volatile("cp.async.wait_group 1;" ::: "memory")
#define CP_WAIT2()  asm volatile("cp.async.wait_group 2;" ::: "memory")

__device__ __forceinline__ void mma16816(float* c, const uint32_t* a,
                                         uint32_t b0, uint32_t b1)
{
    asm volatile(
        "mma.sync.aligned.m16n8k16.row.col.f32.f16.f16.f32 "
        "{%0,%1,%2,%3}, {%4,%5,%6,%7}, {%8,%9}, {%0,%1,%2,%3};"
        : "+f"(c[0]), "+f"(c[1]), "+f"(c[2]), "+f"(c[3])
        : "r"(a[0]), "r"(a[1]), "r"(a[2]), "r"(a[3]), "r"(b0), "r"(b1));
}
__device__ __forceinline__ void ldsm4(uint32_t* r, uint32_t addr) {
    asm volatile("ldmatrix.sync.aligned.m8n8.x4.shared.b16 {%0,%1,%2,%3}, [%4];"
                 : "=r"(r[0]), "=r"(r[1]), "=r"(r[2]), "=r"(r[3]) : "r"(addr));
}
__device__ __forceinline__ void ldsm2(uint32_t* r, uint32_t addr) {
    asm volatile("ldmatrix.sync.aligned.m8n8.x2.shared.b16 {%0,%1}, [%2];"
                 : "=r"(r[0]), "=r"(r[1]) : "r"(addr));
}
__device__ __forceinline__ unsigned ld_acq(unsigned* p) {
    unsigned v;
    asm volatile("ld.acquire.gpu.u32 %0, [%1];" : "=r"(v) : "l"(p));
    return v;
}
__device__ __forceinline__ void grid_bar(unsigned target) {
    __syncthreads();
    if (threadIdx.x == 0) {
        __threadfence();
        atomicAdd(&g_barctr, 1u);
        while (ld_acq(&g_barctr) < target) {}
        __threadfence();
    }
    __syncthreads();
}
__device__ __forceinline__ void split16(float x, __half& hi, __half& lo) {
    hi = __float2half_rn(x);
    lo = __float2half_rn(x - __half2float(hi));
}

// ===========================================================================
// sort rows by stop length (descending) -> g_perm, g_sl, g_nact. 1 CTA.
// ===========================================================================
__global__ void sort_kernel(const int* __restrict__ actions,
                            const int* __restrict__ stop_idx)
{
    __shared__ int counts[TT + 1];
    __shared__ int start[TT + 1];
    int tid = threadIdx.x;
    if (tid <= TT) counts[tid] = 0;
    __syncthreads();

    int si = stop_idx[tid];
    int sl = TT;
    for (int t = 0; t < TT; t++) {
        int a = actions[tid * TT + t];
        if (a < 0 || a == si) { sl = t; break; }
    }
    atomicAdd(&counts[sl], 1);
    __syncthreads();
    if (tid == 0) {
        int acc = 0;
        for (int s = TT; s >= 0; s--) { start[s] = acc; acc += counts[s]; }
        for (int t = 0; t < TT; t++) g_nact[t] = start[t];  // #rows with sl > t
        g_barctr = 0;
    }
    __syncthreads();
    int pos = atomicAdd(&start[sl], 1);
    g_perm[pos] = tid;
    g_sl[pos] = sl;
}

// ===========================================================================
// Big GEMM (gi): out[M, H3] = A x B^T + bias ; tile 128x128
// ===========================================================================
__global__ __launch_bounds__(256)
void gemm_big(const __half* __restrict__ A,
              const __half* __restrict__ B,
              const float* __restrict__ bias,
              float* __restrict__ out)
{
    const int col0 = blockIdx.x * BBN;
    const int row0 = blockIdx.y * BBM;
    if ((row0 & 1023) >= g_nact[row0 >> 10]) return;   // rows never consumed

    extern __shared__ __align__(16) char dsm[];
    const uint32_t sbase = smem_u32(dsm);

    const int tid  = threadIdx.x;
    const int lane = tid & 31;
    const int w    = tid >> 5;
    const int wr   = w & 1;
    const int wc   = w >> 1;
    const int qr   = lane >> 2;
    const int qc   = lane & 3;

    const __half* srcp[4];
    uint32_t soff[4];
    #pragma unroll
    for (int j = 0; j < 4; j++) {
        int idx  = tid + 256 * j;
        int arow = idx >> 2;
        int seg  = (idx & 3) * 8;
        if (arow < BBM) {
            srcp[j] = A + (size_t)(row0 + arow) * KTOT + seg;
            soff[j] = (uint32_t)(arow * SA + seg) * 2;
        } else {
            int brow = arow - BBM;
            srcp[j] = B + (size_t)(col0 + brow) * KTOT + seg;
            soff[j] = (uint32_t)((BBM + brow) * SA + seg) * 2;
        }
    }

    uint32_t aoff[4], boff[2];
    #pragma unroll
    for (int mi = 0; mi < 4; mi++)
        aoff[mi] = (uint32_t)((wr * 64 + mi * 16 + (lane & 7) + 8 * ((lane >> 3) & 1)) * SA
                              + 8 * (lane >> 4)) * 2;
    #pragma unroll
    for (int p = 0; p < 2; p++)
        boff[p] = (uint32_t)((BBM + wc * 32 + p * 16 + (lane & 7) + 8 * (lane >> 4)) * SA
                             + 8 * ((lane >> 3) & 1)) * 2;

    float acc[4][4][4];
    #pragma unroll
    for (int i = 0; i < 4; i++)
        #pragma unroll
        for (int j = 0; j < 4; j++)
            #pragma unroll
            for (int v = 0; v < 4; v++) acc[i][j][v] = 0.0f;

    #pragma unroll
    for (int s = 0; s < NSTAGE - 1; s++) {
        uint32_t sb = sbase + s * BSTAGE;
        #pragma unroll
        for (int j = 0; j < 4; j++) CP_ASYNC16(sb + soff[j], srcp[j] + s * BK);
        CP_COMMIT();
    }

    #pragma unroll 1
    for (int kt = 0; kt < KITERS; kt++) {
        if (kt < KITERS - 2)       CP_WAIT2();
        else if (kt == KITERS - 2) CP_WAIT1();
        else                       CP_WAIT0();
        __syncthreads();

        if (kt + NSTAGE - 1 < KITERS) {
            int kc = kt + NSTAGE - 1;
            uint32_t sb = sbase + (kc & (NSTAGE - 1)) * BSTAGE;
            #pragma unroll
            for (int j = 0; j < 4; j++) CP_ASYNC16(sb + soff[j], srcp[j] + kc * BK);
            CP_COMMIT();
        }

        uint32_t sst = sbase + (kt & (NSTAGE - 1)) * BSTAGE;
        #pragma unroll
        for (int ks = 0; ks < 2; ks++) {
            uint32_t kb2 = ks * 32;
            uint32_t af[4][4], bf[2][4];
            #pragma unroll
            for (int mi = 0; mi < 4; mi++) ldsm4(af[mi], sst + aoff[mi] + kb2);
            #pragma unroll
            for (int p = 0; p < 2; p++)    ldsm4(bf[p], sst + boff[p] + kb2);
            #pragma unroll
            for (int ni = 0; ni < 4; ni++) {
                uint32_t b0 = bf[ni >> 1][(ni & 1) * 2];
                uint32_t b1 = bf[ni >> 1][(ni & 1) * 2 + 1];
                #pragma unroll
                for (int mi = 0; mi < 4; mi++)
                    mma16816(acc[mi][ni], af[mi], b0, b1);
            }
        }
        __syncthreads();
    }

    #pragma unroll
    for (int mi = 0; mi < 4; mi++) {
        int r = row0 + wr * 64 + mi * 16 + qr;
        #pragma unroll
        for (int ni = 0; ni < 4; ni++) {
            int c = col0 + wc * 32 + ni * 8 + qc * 2;
            float2 bv = *(const float2*)(bias + c);
            float2 v0 = make_float2(acc[mi][ni][0] + bv.x, acc[mi][ni][1] + bv.y);
            float2 v1 = make_float2(acc[mi][ni][2] + bv.x, acc[mi][ni][3] + bv.y);
            *(float2*)(out + (size_t)r * H3 + c)       = v0;
            *(float2*)(out + (size_t)(r + 8) * H3 + c) = v1;
        }
    }
}

// ===========================================================================
// Persistent loop: 256 CTAs (2/SM), tile 64x96, K=1024, BK=64, 4-stage.
// Prologue issued before LN (overlap). Frozen rows: no copies.
// ===========================================================================
__global__ __launch_bounds__(256, 2)
void persist_loop(const float* __restrict__ ln_w,
                  const float* __restrict__ ln_b,
                  const float* __restrict__ b_hh,
                  float* __restrict__ out)
{
    extern __shared__ __align__(16) char dsm[];
    const uint32_t sbase = smem_u32(dsm);

    const int tid   = threadIdx.x;
    const int lane  = tid & 31;
    const int w     = tid >> 5;
    const int wr    = w & 1;
    const int wc    = w >> 1;
    const int qr    = lane >> 2;
    const int qc    = lane & 3;
    const int cid   = blockIdx.x;
    const int ntile = cid & 15;
    const int mtile = cid >> 4;
    const int row0  = mtile * LBM;
    const int col0  = ntile * LBN;
    const int hid0  = ntile * 32;

    int orig_ln = 0, sl_ln = 0;
    if (w < 4) {
        orig_ln = g_perm[cid * 4 + w];
        sl_ln   = g_sl[cid * 4 + w];
    }

    // loader mapping: 160 rows x 8 chunks = 1280 = 256 x 5
    size_t  goff[5];
    uint32_t soff[5];
    bool isA[5];
    #pragma unroll
    for (int j = 0; j < 5; j++) {
        int idx = tid + 256 * j;
        int row = idx >> 3;
        int seg = (idx & 7) * 8;
        isA[j] = (row < LBM);
        if (row < LBM) goff[j] = (size_t)(row0 + row) * KTOT + seg;
        else           goff[j] = (size_t)(col0 + row - LBM) * KTOT + seg;
        soff[j] = (uint32_t)(row * LSA + seg) * 2;
    }

    uint32_t aoff[2], boff4, boff2;
    #pragma unroll
    for (int mi = 0; mi < 2; mi++)
        aoff[mi] = (uint32_t)((wr * 32 + mi * 16 + (lane & 7) + 8 * ((lane >> 3) & 1)) * LSA
                              + 8 * (lane >> 4)) * 2;
    boff4 = (uint32_t)((LBM + wc * 24 + (lane & 7) + 8 * (lane >> 4)) * LSA
                       + 8 * ((lane >> 3) & 1)) * 2;
    boff2 = (uint32_t)((LBM + wc * 24 + 16 + (lane & 7)) * LSA
                       + 8 * ((lane >> 3) & 1)) * 2;

    unsigned ph = 0;

    #pragma unroll 1
    for (int t = 0; t < TT; t++) {
        const int cur = t & 1;
        const int nxt = cur ^ 1;
        const __half* h2cur = g_h2[cur];
        const int nact = g_nact[t];
        const bool tile_active = (row0 < nact) && (t < TT - 1);

        // ---------- issue GEMM prologue first (overlaps LN with load latency)
        if (tile_active) {
            #pragma unroll
            for (int s = 0; s < LNST - 1; s++) {
                uint32_t sb = sbase + s * LSTAGE;
                #pragma unroll
                for (int j = 0; j < 5; j++) {
                    const __half* p = (isA[j] ? h2cur : g_W2hh) + goff[j] + s * LBK;
                    CP_ASYNC16(sb + soff[j], p);
                }
                CP_COMMIT();
            }
        }

        // ---------- LN emit: warps 0..3, one row each ----------
        if (w < 4) {
            int rown = cid * 4 + w;
            int e = t < sl_ln ? t : sl_ln;
            const float* hp = g_h[e & 1] + (size_t)rown * HD;
            float4 v[4];
            #pragma unroll
            for (int j = 0; j < 4; j++) v[j] = ((const float4*)hp)[lane + 32 * j];
            float s = 0.0f;
            #pragma unroll
            for (int j = 0; j < 4; j++) s += v[j].x + v[j].y + v[j].z + v[j].w;
            #pragma unroll
            for (int o = 16; o > 0; o >>= 1) s += __shfl_xor_sync(0xffffffffu, s, o);
            float mean = s * (1.0f / HD);
            float q = 0.0f;
            #pragma unroll
            for (int j = 0; j < 4; j++) {
                float a0 = v[j].x - mean, a1 = v[j].y - mean;
                float a2 = v[j].z - mean, a3 = v[j].w - mean;
                q += a0 * a0 + a1 * a1 + a2 * a2 + a3 * a3;
            }
            #pragma unroll
            for (int o = 16; o > 0; o >>= 1) q += __shfl_xor_sync(0xffffffffu, q, o);
            float rstd = rsqrtf(q * (1.0f / HD) + LN_EPS);
            float* orow = out + ((size_t)orig_ln * TT + t) * HD;
            #pragma unroll
            for (int j = 0; j < 4; j++) {
                float4 lw = ((const float4*)ln_w)[lane + 32 * j];
                float4 lb = ((const float4*)ln_b)[lane + 32 * j];
                float4 o;
                o.x = (v[j].x - mean) * rstd * lw.x + lb.x;
                o.y = (v[j].y - mean) * rstd * lw.y + lb.y;
                o.z = (v[j].z - mean) * rstd * lw.z + lb.z;
                o.w = (v[j].w - mean) * rstd * lw.w + lb.w;
                ((float4*)orow)[lane + 32 * j] = o;
            }
        }
        if (t == TT - 1) break;

        float* sst = (float*)dsm;

        if (tile_active) {
            // ---------- gh GEMM (64x96, K=1024, BK=64, 4-stage) ----------
            float acc[2][3][4];
            #pragma unroll
            for (int i = 0; i < 2; i++)
                #pragma unroll
                for (int j = 0; j < 3; j++)
                    #pragma unroll
                    for (int v = 0; v < 4; v++) acc[i][j][v] = 0.0f;

            #pragma unroll 1
            for (int kt = 0; kt < LKIT; kt++) {
                if (kt < LKIT - 2)       CP_WAIT2();
                else if (kt == LKIT - 2) CP_WAIT1();
                else                     CP_WAIT0();
                __syncthreads();

                if (kt + LNST - 1 < LKIT) {
                    int kc = kt + LNST - 1;
                    uint32_t sb = sbase + (kc & (LNST - 1)) * LSTAGE;
                    #pragma unroll
                    for (int j = 0; j < 5; j++) {
                        const __half* p = (isA[j] ? h2cur : g_W2hh) + goff[j] + kc * LBK;
                        CP_ASYNC16(sb + soff[j], p);
                    }
                    CP_COMMIT();
                }

                uint32_t sstage = sbase + (kt & (LNST - 1)) * LSTAGE;
                #pragma unroll
                for (int ks = 0; ks < 4; ks++) {
                    uint32_t kb2 = ks * 32;
                    uint32_t af[2][4], bfa[4], bfb[2];
                    #pragma unroll
                    for (int mi = 0; mi < 2; mi++) ldsm4(af[mi], sstage + aoff[mi] + kb2);
                    ldsm4(bfa, sstage + boff4 + kb2);
                    ldsm2(bfb, sstage + boff2 + kb2);
                    #pragma unroll
                    for (int ni = 0; ni < 3; ni++) {
                        uint32_t b0 = (ni < 2) ? bfa[ni * 2]     : bfb[0];
                        uint32_t b1 = (ni < 2) ? bfa[ni * 2 + 1] : bfb[1];
                        #pragma unroll
                        for (int mi = 0; mi < 2; mi++)
                            mma16816(acc[mi][ni], af[mi], b0, b1);
                    }
                }
                __syncthreads();
            }

            // stage accumulators to smem
            #pragma unroll
            for (int mi = 0; mi < 2; mi++) {
                int r = wr * 32 + mi * 16 + qr;
                #pragma unroll
                for (int ni = 0; ni < 3; ni++) {
                    int c = wc * 24 + ni * 8 + qc * 2;
                    sst[r * SSTR + c]           = acc[mi][ni][0];
                    sst[r * SSTR + c + 1]       = acc[mi][ni][1];
                    sst[(r + 8) * SSTR + c]     = acc[mi][ni][2];
                    sst[(r + 8) * SSTR + c + 1] = acc[mi][ni][3];
                }
            }
            __syncthreads();

            // ---------- GRU update (active rows only) ----------
            const float* hcur = g_h[cur];
            float*  hnb  = g_h[nxt];
            __half* h2nb = g_h2[nxt];
            #pragma unroll
            for (int k = 0; k < (LBM * 32) / 256; k++) {
                int idx = tid + k * 256;
                int rl  = idx >> 5;
                int j   = idx & 31;
                int b   = row0 + rl;
                int hid = hid0 + j;
                if (b >= nact) continue;

                float ghr = sst[rl * SSTR + 3 * j];
                float ghz = sst[rl * SSTR + 3 * j + 1];
                float ghn = sst[rl * SSTR + 3 * j + 2];
                const float* gip = g_gi + ((size_t)t * BQ + b) * H3 + col0 + 3 * j;
                float hold = hcur[(size_t)b * HD + hid];
                float r = 1.0f / (1.0f + expf(-(gip[0] + ghr)));
                float z = 1.0f / (1.0f + expf(-(gip[1] + ghz)));
                float n = tanhf(gip[2] + r * (ghn + b_hh[1024 + hid]));
                float hnew = (1.0f - z) * n + z * hold;

                hnb[(size_t)b * HD + hid] = hnew;
                __half hi, lo; split16(hnew, hi, lo);
                __half* h2row = h2nb + (size_t)b * KTOT;
                h2row[hid]      = hi;
                h2row[HD + hid] = lo;
            }
        }
        grid_bar(++ph * PCTAS);
    }
}

// ===========================================================================
// prep kernels
// ===========================================================================
__global__ void prep_weights(const float* __restrict__ wih,
                             const float* __restrict__ whh)
{
    int n = blockIdx.x;
    int g = n >> 9, i = n & 511;
    int np = 3 * i + g;
    const float* src = (blockIdx.y == 0 ? wih : whh) + (size_t)n * HD;
    __half* dst = (blockIdx.y == 0 ? g_W2ih : g_W2hh) + (size_t)np * KTOT;
    for (int k = threadIdx.x; k < HD; k += 128) {
        __half hi = __float2half_rn(src[k]);
        dst[k] = hi; dst[HD + k] = hi;
    }
}

__global__ void prep_bias(const float* __restrict__ b_ih,
                          const float* __restrict__ b_hh)
{
    int x = blockIdx.x * 256 + threadIdx.x;
    if (x < H3) {
        int g = x >> 9, i = x & 511;
        g_bsum[3 * i + g] = b_ih[x] + (g < 2 ? b_hh[x] : 0.0f);
    }
}

__global__ void prep_agi(const int* __restrict__ actions,
                         const float* __restrict__ edge_tokens, int E)
{
    int m = blockIdx.x;
    int t = m >> 10, nb = m & (BQ - 1);
    if (nb >= g_nact[t]) return;
    int b = g_perm[nb];
    int a = actions[b * TT + t];
    a = a < 0 ? 0 : (a >= E ? E - 1 : a);
    const float* src = edge_tokens + (size_t)a * HD;
    __half* dst = g_Agi + (size_t)m * KTOT;
    for (int k = threadIdx.x; k < HD; k += 128) {
        __half hi, lo; split16(src[k], hi, lo);
        dst[k] = hi; dst[HD + k] = lo;
    }
}

// ===========================================================================
// init
// ===========================================================================
__device__ __forceinline__ float block_sum_256(float v, float* red)
{
    int lane = threadIdx.x & 31, w = threadIdx.x >> 5;
    #pragma unroll
    for (int o = 16; o > 0; o >>= 1) v += __shfl_xor_sync(0xffffffffu, v, o);
    if (lane == 0) red[w] = v;
    __syncthreads();
    if (w == 0) {
        float x = (lane < 8) ? red[lane] : 0.0f;
        #pragma unroll
        for (int o = 4; o > 0; o >>= 1) x += __shfl_xor_sync(0xffffffffu, x, o);
        if (lane == 0) red[0] = x;
    }
    __syncthreads();
    float r = red[0];
    __syncthreads();
    return r;
}

__global__ void init_kernel(const float* __restrict__ question,
                            const float* __restrict__ node_tokens,
                            const int*   __restrict__ locals,
                            const int*   __restrict__ ptr,
                            const float* __restrict__ ln_w,
                            const float* __restrict__ ln_b)
{
    __shared__ float red[8];
    int nb = blockIdx.x, tid = threadIdx.x;
    int b = g_perm[nb];
    int p0 = ptr[b], p1 = ptr[b + 1];
    int cnt = p1 - p0;
    float inv = 1.0f / (float)(cnt > 0 ? cnt : 1);

    float s0 = 0.0f, s1 = 0.0f;
    for (int j = p0; j < p1; j++) {
        const float* nrow = node_tokens + (size_t)locals[j] * HD;
        s0 += nrow[tid]; s1 += nrow[tid + 256];
    }
    const float* q = question + (size_t)b * HD;
    float x0 = q[tid] + s0 * inv, x1 = q[tid + 256] + s1 * inv;

    float mean = block_sum_256(x0 + x1, red) * (1.0f / HD);
    float d0 = x0 - mean, d1 = x1 - mean;
    float var = block_sum_256(d0 * d0 + d1 * d1, red) * (1.0f / HD);
    float rstd = rsqrtf(var + LN_EPS);

    float v0 = d0 * rstd * ln_w[tid] + ln_b[tid];
    float v1 = d1 * rstd * ln_w[tid + 256] + ln_b[tid + 256];
    float* hrow = g_h[0] + (size_t)nb * HD;
    hrow[tid] = v0; hrow[tid + 256] = v1;

    __half* h2row = g_h2[0] + (size_t)nb * KTOT;
    __half hi, lo;
    split16(v0, hi, lo);
    h2row[tid] = hi; h2row[HD + tid] = lo;
    split16(v1, hi, lo);
    h2row[tid + 256] = hi; h2row[HD + tid + 256] = lo;
}

// ===========================================================================
// launch
// ===========================================================================
extern "C" void kernel_launch(void* const* d_in, const int* in_sizes, int n_in,
                              void* d_out, int out_size)
{
    const int*   actions      = (const int*)  d_in[0];
    const float* edge_tokens  = (const float*)d_in[1];
    const int*   stop_indices = (const int*)  d_in[2];
    const float* question     = (const float*)d_in[3];
    const float* node_tokens  = (const float*)d_in[4];
    const int*   start_locals = (const int*)  d_in[5];
    const int*   start_ptr    = (const int*)  d_in[6];
    const float* w_ih         = (const float*)d_in[7];
    const float* w_hh         = (const float*)d_in[8];
    const float* b_ih         = (const float*)d_in[9];
    const float* b_hh         = (const float*)d_in[10];
    const float* ln_w         = (const float*)d_in[11];
    const float* ln_b         = (const float*)d_in[12];
    float* out = (float*)d_out;
    const int E = in_sizes[1] / HD;

    void *pAgi, *pWih, *pGi, *pBsum;
    cudaGetSymbolAddress(&pAgi, g_Agi);
    cudaGetSymbolAddress(&pWih, g_W2ih);
    cudaGetSymbolAddress(&pGi,  g_gi);
    cudaGetSymbolAddress(&pBsum, g_bsum);

    cudaFuncSetAttribute(gemm_big, cudaFuncAttributeMaxDynamicSharedMemorySize, BIG_SMEM);
    cudaFuncSetAttribute(persist_loop, cudaFuncAttributeMaxDynamicSharedMemorySize, LSMEM);

    prep_weights<<<dim3(H3, 2), 128>>>(w_ih, w_hh);
    prep_bias<<<(H3 + 255) / 256, 256>>>(b_ih, b_hh);
    sort_kernel<<<1, 1024>>>(actions, stop_indices);
    prep_agi<<<MGI, 128>>>(actions, edge_tokens, E);
    init_kernel<<<BQ, 256>>>(question, node_tokens, start_locals, start_ptr, ln_w, ln_b);

    gemm_big<<<dim3(H3 / BBN, MGI / BBM), 256, BIG_SMEM>>>(
        (const __half*)pAgi, (const __half*)pWih,
        (const float*)pBsum, (float*)pGi);

    persist_loop<<<PCTAS, 256, LSMEM>>>(ln_w, ln_b, b_hh, out);
}

// round 9
// speedup vs baseline: 2.1839x; 1.1692x over previous
#include <cuda_runtime.h>
#include <cuda_fp16.h>
#include <math.h>
#include <stdint.h>

// ---------------- problem dims ----------------
#define BQ   1024
#define TT   64
#define HD   512
#define H3   1536
#define MGI  (BQ * TT)
#define KTOT 1024               // gi GEMM: K' = 2*512 (fp16x2 split of A; W=[Wh|Wh])
#define KL   512                // loop GEMM: K = 512 (fp16 h, fp16 W)
#define LN_EPS 1e-5f

// ---- big (gi) GEMM tiling ----
#define BK 32
#define KITERS (KTOT / BK)      // 32
#define SA 40
#define NSTAGE 4
#define BBM 128
#define BBN 128
#define BSTAGE ((BBM + BBN) * SA * 2)
#define BIG_SMEM (NSTAGE * BSTAGE)      // 81920

// ---- persistent loop tiling: 64x96, K=512, BK=64, 4 stages, 256 CTAs ----
#define LBM 64
#define LBN 96
#define LBK 64
#define LSA 72
#define LKIT (KL / LBK)                 // 8
#define LROWS (LBM + LBN)               // 160
#define LSTAGE (LROWS * LSA * 2)        // 23040
#define LNST 4
#define LSMEM (LNST * LSTAGE)           // 92160
#define PCTAS 256
#define SSTR 97

// ---------------- device scratch ----------------
__device__ __half g_Agi[(size_t)MGI * KTOT];
__device__ float  g_gi [(size_t)MGI * H3];     // gate-interleaved cols, biases folded
__device__ __half g_W2ih[(size_t)H3 * KTOT];   // gate-interleaved rows, [Wh|Wh]
__device__ __half g_Whh[(size_t)H3 * KL];      // gate-interleaved rows, fp16
__device__ __half g_hh[2][(size_t)BQ * KL];    // ping-pong fp16(h)
__device__ float  g_h [2][(size_t)BQ * HD];
__device__ float  g_bsum[H3];
__device__ int    g_perm[BQ];
__device__ int    g_sl[BQ];
__device__ int    g_nact[TT];
__device__ unsigned int g_barctr[8];

// ---------------- helpers ----------------
__device__ __forceinline__ uint32_t smem_u32(const void* p) {
    uint32_t a;
    asm("{ .reg .u64 t; cvta.to.shared.u64 t, %1; cvt.u32.u64 %0, t; }" : "=r"(a) : "l"(p));
    return a;
}
#define CP_ASYNC16(dst, src) \
    asm volatile("cp.async.cg.shared.global [%0], [%1], 16;" :: "r"(dst), "l"(src))
#define CP_COMMIT() asm volatile("cp.async.commit_group;" ::: "memory")
#define CP_WAIT0()  asm volatile("cp.async.wait_group 0;" ::: "memory")
#define CP_WAIT1()  asm volatile("cp.async.wait_group 1;" ::: "memory")
#define CP_WAIT2()  asm volatile("cp.async.wait_group 2;" ::: "memory")

__device__ __forceinline__ void mma16816(float* c, const uint32_t* a,
                                         uint32_t b0, uint32_t b1)
{
    asm volatile(
        "mma.sync.aligned.m16n8k16.row.col.f32.f16.f16.f32 "
        "{%0,%1,%2,%3}, {%4,%5,%6,%7}, {%8,%9}, {%0,%1,%2,%3};"
        : "+f"(c[0]), "+f"(c[1]), "+f"(c[2]), "+f"(c[3])
        : "r"(a[0]), "r"(a[1]), "r"(a[2]), "r"(a[3]), "r"(b0), "r"(b1));
}
__device__ __forceinline__ void ldsm4(uint32_t* r, uint32_t addr) {
    asm volatile("ldmatrix.sync.aligned.m8n8.x4.shared.b16 {%0,%1,%2,%3}, [%4];"
                 : "=r"(r[0]), "=r"(r[1]), "=r"(r[2]), "=r"(r[3]) : "r"(addr));
}
__device__ __forceinline__ void ldsm2(uint32_t* r, uint32_t addr) {
    asm volatile("ldmatrix.sync.aligned.m8n8.x2.shared.b16 {%0,%1}, [%2];"
                 : "=r"(r[0]), "=r"(r[1]) : "r"(addr));
}
__device__ __forceinline__ unsigned ld_acq(unsigned* p) {
    unsigned v;
    asm volatile("ld.acquire.gpu.u32 %0, [%1];" : "=r"(v) : "l"(p));
    return v;
}
__device__ __forceinline__ void grid_bar(int cid, unsigned target) {
    __syncthreads();
    if (threadIdx.x == 0) {
        __threadfence();
        atomicAdd(&g_barctr[cid & 7], 1u);
        for (;;) {
            unsigned s = 0;
            #pragma unroll
            for (int i = 0; i < 8; i++) s += ld_acq(&g_barctr[i]);
            if (s >= target) break;
        }
        __threadfence();
    }
    __syncthreads();
}
__device__ __forceinline__ void split16(float x, __half& hi, __half& lo) {
    hi = __float2half_rn(x);
    lo = __float2half_rn(x - __half2float(hi));
}

// ===========================================================================
// sort rows by stop length (descending) -> g_perm, g_sl, g_nact. 1 CTA.
// ===========================================================================
__global__ void sort_kernel(const int* __restrict__ actions,
                            const int* __restrict__ stop_idx)
{
    __shared__ int counts[TT + 1];
    __shared__ int start[TT + 1];
    int tid = threadIdx.x;
    if (tid <= TT) counts[tid] = 0;
    __syncthreads();

    int si = stop_idx[tid];
    int sl = TT;
    for (int t = 0; t < TT; t++) {
        int a = actions[tid * TT + t];
        if (a < 0 || a == si) { sl = t; break; }
    }
    atomicAdd(&counts[sl], 1);
    __syncthreads();
    if (tid == 0) {
        int acc = 0;
        for (int s = TT; s >= 0; s--) { start[s] = acc; acc += counts[s]; }
        for (int t = 0; t < TT; t++) g_nact[t] = start[t];
        #pragma unroll
        for (int i = 0; i < 8; i++) g_barctr[i] = 0;
    }
    __syncthreads();
    int pos = atomicAdd(&start[sl], 1);
    g_perm[pos] = tid;
    g_sl[pos] = sl;
}

// ===========================================================================
// Big GEMM (gi): out[M, H3] = A x B^T + bias ; tile 128x128, K=1024
// ===========================================================================
__global__ __launch_bounds__(256)
void gemm_big(const __half* __restrict__ A,
              const __half* __restrict__ B,
              const float* __restrict__ bias,
              float* __restrict__ out)
{
    const int col0 = blockIdx.x * BBN;
    const int row0 = blockIdx.y * BBM;
    if ((row0 & 1023) >= g_nact[row0 >> 10]) return;

    extern __shared__ __align__(16) char dsm[];
    const uint32_t sbase = smem_u32(dsm);

    const int tid  = threadIdx.x;
    const int lane = tid & 31;
    const int w    = tid >> 5;
    const int wr   = w & 1;
    const int wc   = w >> 1;
    const int qr   = lane >> 2;
    const int qc   = lane & 3;

    const __half* srcp[4];
    uint32_t soff[4];
    #pragma unroll
    for (int j = 0; j < 4; j++) {
        int idx  = tid + 256 * j;
        int arow = idx >> 2;
        int seg  = (idx & 3) * 8;
        if (arow < BBM) {
            srcp[j] = A + (size_t)(row0 + arow) * KTOT + seg;
            soff[j] = (uint32_t)(arow * SA + seg) * 2;
        } else {
            int brow = arow - BBM;
            srcp[j] = B + (size_t)(col0 + brow) * KTOT + seg;
            soff[j] = (uint32_t)((BBM + brow) * SA + seg) * 2;
        }
    }

    uint32_t aoff[4], boff[2];
    #pragma unroll
    for (int mi = 0; mi < 4; mi++)
        aoff[mi] = (uint32_t)((wr * 64 + mi * 16 + (lane & 7) + 8 * ((lane >> 3) & 1)) * SA
                              + 8 * (lane >> 4)) * 2;
    #pragma unroll
    for (int p = 0; p < 2; p++)
        boff[p] = (uint32_t)((BBM + wc * 32 + p * 16 + (lane & 7) + 8 * (lane >> 4)) * SA
                             + 8 * ((lane >> 3) & 1)) * 2;

    float acc[4][4][4];
    #pragma unroll
    for (int i = 0; i < 4; i++)
        #pragma unroll
        for (int j = 0; j < 4; j++)
            #pragma unroll
            for (int v = 0; v < 4; v++) acc[i][j][v] = 0.0f;

    #pragma unroll
    for (int s = 0; s < NSTAGE - 1; s++) {
        uint32_t sb = sbase + s * BSTAGE;
        #pragma unroll
        for (int j = 0; j < 4; j++) CP_ASYNC16(sb + soff[j], srcp[j] + s * BK);
        CP_COMMIT();
    }

    #pragma unroll 1
    for (int kt = 0; kt < KITERS; kt++) {
        if (kt < KITERS - 2)       CP_WAIT2();
        else if (kt == KITERS - 2) CP_WAIT1();
        else                       CP_WAIT0();
        __syncthreads();

        if (kt + NSTAGE - 1 < KITERS) {
            int kc = kt + NSTAGE - 1;
            uint32_t sb = sbase + (kc & (NSTAGE - 1)) * BSTAGE;
            #pragma unroll
            for (int j = 0; j < 4; j++) CP_ASYNC16(sb + soff[j], srcp[j] + kc * BK);
            CP_COMMIT();
        }

        uint32_t sst = sbase + (kt & (NSTAGE - 1)) * BSTAGE;
        #pragma unroll
        for (int ks = 0; ks < 2; ks++) {
            uint32_t kb2 = ks * 32;
            uint32_t af[4][4], bf[2][4];
            #pragma unroll
            for (int mi = 0; mi < 4; mi++) ldsm4(af[mi], sst + aoff[mi] + kb2);
            #pragma unroll
            for (int p = 0; p < 2; p++)    ldsm4(bf[p], sst + boff[p] + kb2);
            #pragma unroll
            for (int ni = 0; ni < 4; ni++) {
                uint32_t b0 = bf[ni >> 1][(ni & 1) * 2];
                uint32_t b1 = bf[ni >> 1][(ni & 1) * 2 + 1];
                #pragma unroll
                for (int mi = 0; mi < 4; mi++)
                    mma16816(acc[mi][ni], af[mi], b0, b1);
            }
        }
        __syncthreads();
    }

    #pragma unroll
    for (int mi = 0; mi < 4; mi++) {
        int r = row0 + wr * 64 + mi * 16 + qr;
        #pragma unroll
        for (int ni = 0; ni < 4; ni++) {
            int c = col0 + wc * 32 + ni * 8 + qc * 2;
            float2 bv = *(const float2*)(bias + c);
            float2 v0 = make_float2(acc[mi][ni][0] + bv.x, acc[mi][ni][1] + bv.y);
            float2 v1 = make_float2(acc[mi][ni][2] + bv.x, acc[mi][ni][3] + bv.y);
            *(float2*)(out + (size_t)r * H3 + c)       = v0;
            *(float2*)(out + (size_t)(r + 8) * H3 + c) = v1;
        }
    }
}

// ===========================================================================
// Persistent loop: 256 CTAs (2/SM), tile 64x96, K=512, BK=64, 4-stage.
// ===========================================================================
__global__ __launch_bounds__(256, 2)
void persist_loop(const float* __restrict__ ln_w,
                  const float* __restrict__ ln_b,
                  const float* __restrict__ b_hh,
                  float* __restrict__ out)
{
    extern __shared__ __align__(16) char dsm[];
    const uint32_t sbase = smem_u32(dsm);

    const int tid   = threadIdx.x;
    const int lane  = tid & 31;
    const int w     = tid >> 5;
    const int wr    = w & 1;
    const int wc    = w >> 1;
    const int qr    = lane >> 2;
    const int qc    = lane & 3;
    const int cid   = blockIdx.x;
    const int ntile = cid & 15;
    const int mtile = cid >> 4;
    const int row0  = mtile * LBM;
    const int col0  = ntile * LBN;
    const int hid0  = ntile * 32;

    int orig_ln = 0, sl_ln = 0;
    if (w < 4) {
        orig_ln = g_perm[cid * 4 + w];
        sl_ln   = g_sl[cid * 4 + w];
    }

    // loader mapping: 160 rows x 8 chunks = 1280 = 256 x 5
    size_t  goff[5];
    uint32_t soff[5];
    bool isA[5];
    #pragma unroll
    for (int j = 0; j < 5; j++) {
        int idx = tid + 256 * j;
        int row = idx >> 3;
        int seg = (idx & 7) * 8;
        isA[j] = (row < LBM);
        if (row < LBM) goff[j] = (size_t)(row0 + row) * KL + seg;
        else           goff[j] = (size_t)(col0 + row - LBM) * KL + seg;
        soff[j] = (uint32_t)(row * LSA + seg) * 2;
    }

    uint32_t aoff[2], boff4, boff2;
    #pragma unroll
    for (int mi = 0; mi < 2; mi++)
        aoff[mi] = (uint32_t)((wr * 32 + mi * 16 + (lane & 7) + 8 * ((lane >> 3) & 1)) * LSA
                              + 8 * (lane >> 4)) * 2;
    boff4 = (uint32_t)((LBM + wc * 24 + (lane & 7) + 8 * (lane >> 4)) * LSA
                       + 8 * ((lane >> 3) & 1)) * 2;
    boff2 = (uint32_t)((LBM + wc * 24 + 16 + (lane & 7)) * LSA
                       + 8 * ((lane >> 3) & 1)) * 2;

    unsigned ph = 0;

    #pragma unroll 1
    for (int t = 0; t < TT; t++) {
        const int cur = t & 1;
        const int nxt = cur ^ 1;
        const __half* hhcur = g_hh[cur];
        const int nact = g_nact[t];
        const bool tile_active = (row0 < nact) && (t < TT - 1);

        // issue GEMM prologue first (overlaps LN with load latency)
        if (tile_active) {
            #pragma unroll
            for (int s = 0; s < LNST - 1; s++) {
                uint32_t sb = sbase + s * LSTAGE;
                #pragma unroll
                for (int j = 0; j < 5; j++) {
                    const __half* p = (isA[j] ? hhcur : g_Whh) + goff[j] + s * LBK;
                    CP_ASYNC16(sb + soff[j], p);
                }
                CP_COMMIT();
            }
        }

        // ---------- LN emit: warps 0..3, one row each ----------
        if (w < 4) {
            int rown = cid * 4 + w;
            int e = t < sl_ln ? t : sl_ln;
            const float* hp = g_h[e & 1] + (size_t)rown * HD;
            float4 v[4];
            #pragma unroll
            for (int j = 0; j < 4; j++) v[j] = ((const float4*)hp)[lane + 32 * j];
            float s = 0.0f;
            #pragma unroll
            for (int j = 0; j < 4; j++) s += v[j].x + v[j].y + v[j].z + v[j].w;
            #pragma unroll
            for (int o = 16; o > 0; o >>= 1) s += __shfl_xor_sync(0xffffffffu, s, o);
            float mean = s * (1.0f / HD);
            float q = 0.0f;
            #pragma unroll
            for (int j = 0; j < 4; j++) {
                float a0 = v[j].x - mean, a1 = v[j].y - mean;
                float a2 = v[j].z - mean, a3 = v[j].w - mean;
                q += a0 * a0 + a1 * a1 + a2 * a2 + a3 * a3;
            }
            #pragma unroll
            for (int o = 16; o > 0; o >>= 1) q += __shfl_xor_sync(0xffffffffu, q, o);
            float rstd = rsqrtf(q * (1.0f / HD) + LN_EPS);
            float* orow = out + ((size_t)orig_ln * TT + t) * HD;
            #pragma unroll
            for (int j = 0; j < 4; j++) {
                float4 lw = ((const float4*)ln_w)[lane + 32 * j];
                float4 lb = ((const float4*)ln_b)[lane + 32 * j];
                float4 o;
                o.x = (v[j].x - mean) * rstd * lw.x + lb.x;
                o.y = (v[j].y - mean) * rstd * lw.y + lb.y;
                o.z = (v[j].z - mean) * rstd * lw.z + lb.z;
                o.w = (v[j].w - mean) * rstd * lw.w + lb.w;
                ((float4*)orow)[lane + 32 * j] = o;
            }
        }
        if (t == TT - 1) break;

        float* sst = (float*)dsm;

        if (tile_active) {
            // ---------- gh GEMM (64x96, K=512, BK=64, 4-stage) ----------
            float acc[2][3][4];
            #pragma unroll
            for (int i = 0; i < 2; i++)
                #pragma unroll
                for (int j = 0; j < 3; j++)
                    #pragma unroll
                    for (int v = 0; v < 4; v++) acc[i][j][v] = 0.0f;

            #pragma unroll 1
            for (int kt = 0; kt < LKIT; kt++) {
                if (kt < LKIT - 2)       CP_WAIT2();
                else if (kt == LKIT - 2) CP_WAIT1();
                else                     CP_WAIT0();
                __syncthreads();

                if (kt + LNST - 1 < LKIT) {
                    int kc = kt + LNST - 1;
                    uint32_t sb = sbase + (kc & (LNST - 1)) * LSTAGE;
                    #pragma unroll
                    for (int j = 0; j < 5; j++) {
                        const __half* p = (isA[j] ? hhcur : g_Whh) + goff[j] + kc * LBK;
                        CP_ASYNC16(sb + soff[j], p);
                    }
                    CP_COMMIT();
                }

                uint32_t sstage = sbase + (kt & (LNST - 1)) * LSTAGE;
                #pragma unroll
                for (int ks = 0; ks < 4; ks++) {
                    uint32_t kb2 = ks * 32;
                    uint32_t af[2][4], bfa[4], bfb[2];
                    #pragma unroll
                    for (int mi = 0; mi < 2; mi++) ldsm4(af[mi], sstage + aoff[mi] + kb2);
                    ldsm4(bfa, sstage + boff4 + kb2);
                    ldsm2(bfb, sstage + boff2 + kb2);
                    #pragma unroll
                    for (int ni = 0; ni < 3; ni++) {
                        uint32_t b0 = (ni < 2) ? bfa[ni * 2]     : bfb[0];
                        uint32_t b1 = (ni < 2) ? bfa[ni * 2 + 1] : bfb[1];
                        #pragma unroll
                        for (int mi = 0; mi < 2; mi++)
                            mma16816(acc[mi][ni], af[mi], b0, b1);
                    }
                }
                __syncthreads();
            }

            // stage accumulators to smem
            #pragma unroll
            for (int mi = 0; mi < 2; mi++) {
                int r = wr * 32 + mi * 16 + qr;
                #pragma unroll
                for (int ni = 0; ni < 3; ni++) {
                    int c = wc * 24 + ni * 8 + qc * 2;
                    sst[r * SSTR + c]           = acc[mi][ni][0];
                    sst[r * SSTR + c + 1]       = acc[mi][ni][1];
                    sst[(r + 8) * SSTR + c]     = acc[mi][ni][2];
                    sst[(r + 8) * SSTR + c + 1] = acc[mi][ni][3];
                }
            }
            __syncthreads();

            // ---------- GRU update (active rows only) ----------
            const float* hcur = g_h[cur];
            float*  hnb  = g_h[nxt];
            __half* hhnb = g_hh[nxt];
            #pragma unroll
            for (int k = 0; k < (LBM * 32) / 256; k++) {
                int idx = tid + k * 256;
                int rl  = idx >> 5;
                int j   = idx & 31;
                int b   = row0 + rl;
                int hid = hid0 + j;
                if (b >= nact) continue;

                float ghr = sst[rl * SSTR + 3 * j];
                float ghz = sst[rl * SSTR + 3 * j + 1];
                float ghn = sst[rl * SSTR + 3 * j + 2];
                const float* gip = g_gi + ((size_t)t * BQ + b) * H3 + col0 + 3 * j;
                float hold = hcur[(size_t)b * HD + hid];
                float r = 1.0f / (1.0f + expf(-(gip[0] + ghr)));
                float z = 1.0f / (1.0f + expf(-(gip[1] + ghz)));
                float n = tanhf(gip[2] + r * (ghn + b_hh[1024 + hid]));
                float hnew = (1.0f - z) * n + z * hold;

                hnb[(size_t)b * HD + hid] = hnew;
                hhnb[(size_t)b * KL + hid] = __float2half_rn(hnew);
            }
        }
        grid_bar(cid, ++ph * PCTAS);
    }
}

// ===========================================================================
// prep kernels
// ===========================================================================
__global__ void prep_weights(const float* __restrict__ wih,
                             const float* __restrict__ whh)
{
    int n = blockIdx.x;
    int g = n >> 9, i = n & 511;
    int np = 3 * i + g;
    if (blockIdx.y == 0) {
        const float* src = wih + (size_t)n * HD;
        __half* dst = g_W2ih + (size_t)np * KTOT;
        for (int k = threadIdx.x; k < HD; k += 128) {
            __half hi = __float2half_rn(src[k]);
            dst[k] = hi; dst[HD + k] = hi;
        }
    } else {
        const float* src = whh + (size_t)n * HD;
        __half* dst = g_Whh + (size_t)np * KL;
        for (int k = threadIdx.x; k < HD; k += 128)
            dst[k] = __float2half_rn(src[k]);
    }
}

__global__ void prep_bias(const float* __restrict__ b_ih,
                          const float* __restrict__ b_hh)
{
    int x = blockIdx.x * 256 + threadIdx.x;
    if (x < H3) {
        int g = x >> 9, i = x & 511;
        g_bsum[3 * i + g] = b_ih[x] + (g < 2 ? b_hh[x] : 0.0f);
    }
}

__global__ void prep_agi(const int* __restrict__ actions,
                         const float* __restrict__ edge_tokens, int E)
{
    int m = blockIdx.x;
    int t = m >> 10, nb = m & (BQ - 1);
    if (nb >= g_nact[t]) return;
    int b = g_perm[nb];
    int a = actions[b * TT + t];
    a = a < 0 ? 0 : (a >= E ? E - 1 : a);
    const float* src = edge_tokens + (size_t)a * HD;
    __half* dst = g_Agi + (size_t)m * KTOT;
    for (int k = threadIdx.x; k < HD; k += 128) {
        __half hi, lo; split16(src[k], hi, lo);
        dst[k] = hi; dst[HD + k] = lo;
    }
}

// ===========================================================================
// init
// ===========================================================================
__device__ __forceinline__ float block_sum_256(float v, float* red)
{
    int lane = threadIdx.x & 31, w = threadIdx.x >> 5;
    #pragma unroll
    for (int o = 16; o > 0; o >>= 1) v += __shfl_xor_sync(0xffffffffu, v, o);
    if (lane == 0) red[w] = v;
    __syncthreads();
    if (w == 0) {
        float x = (lane < 8) ? red[lane] : 0.0f;
        #pragma unroll
        for (int o = 4; o > 0; o >>= 1) x += __shfl_xor_sync(0xffffffffu, x, o);
        if (lane == 0) red[0] = x;
    }
    __syncthreads();
    float r = red[0];
    __syncthreads();
    return r;
}

__global__ void init_kernel(const float* __restrict__ question,
                            const float* __restrict__ node_tokens,
                            const int*   __restrict__ locals,
                            const int*   __restrict__ ptr,
                            const float* __restrict__ ln_w,
                            const float* __restrict__ ln_b)
{
    __shared__ float red[8];
    int nb = blockIdx.x, tid = threadIdx.x;
    int b = g_perm[nb];
    int p0 = ptr[b], p1 = ptr[b + 1];
    int cnt = p1 - p0;
    float inv = 1.0f / (float)(cnt > 0 ? cnt : 1);

    float s0 = 0.0f, s1 = 0.0f;
    for (int j = p0; j < p1; j++) {
        const float* nrow = node_tokens + (size_t)locals[j] * HD;
        s0 += nrow[tid]; s1 += nrow[tid + 256];
    }
    const float* q = question + (size_t)b * HD;
    float x0 = q[tid] + s0 * inv, x1 = q[tid + 256] + s1 * inv;

    float mean = block_sum_256(x0 + x1, red) * (1.0f / HD);
    float d0 = x0 - mean, d1 = x1 - mean;
    float var = block_sum_256(d0 * d0 + d1 * d1, red) * (1.0f / HD);
    float rstd = rsqrtf(var + LN_EPS);

    float v0 = d0 * rstd * ln_w[tid] + ln_b[tid];
    float v1 = d1 * rstd * ln_w[tid + 256] + ln_b[tid + 256];
    float* hrow = g_h[0] + (size_t)nb * HD;
    hrow[tid] = v0; hrow[tid + 256] = v1;

    __half* hhrow = g_hh[0] + (size_t)nb * KL;
    hhrow[tid]       = __float2half_rn(v0);
    hhrow[tid + 256] = __float2half_rn(v1);
}

// ===========================================================================
// launch
// ===========================================================================
extern "C" void kernel_launch(void* const* d_in, const int* in_sizes, int n_in,
                              void* d_out, int out_size)
{
    const int*   actions      = (const int*)  d_in[0];
    const float* edge_tokens  = (const float*)d_in[1];
    const int*   stop_indices = (const int*)  d_in[2];
    const float* question     = (const float*)d_in[3];
    const float* node_tokens  = (const float*)d_in[4];
    const int*   start_locals = (const int*)  d_in[5];
    const int*   start_ptr    = (const int*)  d_in[6];
    const float* w_ih         = (const float*)d_in[7];
    const float* w_hh         = (const float*)d_in[8];
    const float* b_ih         = (const float*)d_in[9];
    const float* b_hh         = (const float*)d_in[10];
    const float* ln_w         = (const float*)d_in[11];
    const float* ln_b         = (const float*)d_in[12];
    float* out = (float*)d_out;
    const int E = in_sizes[1] / HD;

    void *pAgi, *pWih, *pGi, *pBsum;
    cudaGetSymbolAddress(&pAgi, g_Agi);
    cudaGetSymbolAddress(&pWih, g_W2ih);
    cudaGetSymbolAddress(&pGi,  g_gi);
    cudaGetSymbolAddress(&pBsum, g_bsum);

    cudaFuncSetAttribute(gemm_big, cudaFuncAttributeMaxDynamicSharedMemorySize, BIG_SMEM);
    cudaFuncSetAttribute(persist_loop, cudaFuncAttributeMaxDynamicSharedMemorySize, LSMEM);

    prep_weights<<<dim3(H3, 2), 128>>>(w_ih, w_hh);
    prep_bias<<<(H3 + 255) / 256, 256>>>(b_ih, b_hh);
    sort_kernel<<<1, 1024>>>(actions, stop_indices);
    prep_agi<<<MGI, 128>>>(actions, edge_tokens, E);
    init_kernel<<<BQ, 256>>>(question, node_tokens, start_locals, start_ptr, ln_w, ln_b);

    gemm_big<<<dim3(H3 / BBN, MGI / BBM), 256, BIG_SMEM>>>(
        (const __half*)pAgi, (const __half*)pWih,
        (const float*)pBsum, (float*)pGi);

    persist_loop<<<PCTAS, 256, LSMEM>>>(ln_w, ln_b, b_hh, out);
}